// round 1
// baseline (speedup 1.0000x reference)
#include <cuda_runtime.h>
#include <cstdint>

// Problem constants
#define B_   4
#define F_   16
#define NP_  196
#define DIM_ 512
#define H_   8
#define DH_  64
#define NTOT 3137            // 1 + F*NP
#define MROWS (B_ * NTOT)    // 12548
#define QKVC (3 * H_ * DH_)  // 1536
#define NK_  197             // cls + 196 local keys

// Scratch (allocation-free: __device__ globals)
__device__ float g_qkv[(size_t)MROWS * QKVC];   // ~77 MB
__device__ float g_att[(size_t)MROWS * DIM_];   // ~26 MB

// ---------------------------------------------------------------------------
// SGEMM: C[M,N] = A[M,K] @ B[K,N] (+ bias). 128x128x8 tile, 256 thr, 8x8 micro.
// ---------------------------------------------------------------------------
#define BM 128
#define BN 128
#define BK 8
#define TM 8
#define TN 8

__global__ __launch_bounds__(256, 2)
void sgemm_kernel(const float* __restrict__ A, const float* __restrict__ Bmat,
                  const float* __restrict__ bias, float* __restrict__ C,
                  int M, int N, int K) {
    __shared__ float As[BK][BM];
    __shared__ float Bs[BK][BN];

    const int tid = threadIdx.x;
    const int bm = blockIdx.y * BM;
    const int bn = blockIdx.x * BN;
    const int tx = tid % 16;
    const int ty = tid / 16;

    const int arow = tid >> 1;          // 0..127
    const int acol = (tid & 1) * 4;     // 0 or 4
    const int brow = tid >> 5;          // 0..7
    const int bcol = (tid & 31) * 4;    // 0..124

    float acc[TM][TN];
#pragma unroll
    for (int i = 0; i < TM; i++)
#pragma unroll
        for (int j = 0; j < TN; j++) acc[i][j] = 0.0f;

    for (int k0 = 0; k0 < K; k0 += BK) {
        float4 av = make_float4(0.f, 0.f, 0.f, 0.f);
        if (bm + arow < M)
            av = *(const float4*)&A[(size_t)(bm + arow) * K + k0 + acol];
        As[acol + 0][arow] = av.x;
        As[acol + 1][arow] = av.y;
        As[acol + 2][arow] = av.z;
        As[acol + 3][arow] = av.w;

        float4 bv = make_float4(0.f, 0.f, 0.f, 0.f);
        if (bn + bcol < N)
            bv = *(const float4*)&Bmat[(size_t)(k0 + brow) * N + bn + bcol];
        *(float4*)&Bs[brow][bcol] = bv;

        __syncthreads();

#pragma unroll
        for (int kk = 0; kk < BK; kk++) {
            float a[TM], b[TN];
#pragma unroll
            for (int i = 0; i < TM; i++) a[i] = As[kk][ty * TM + i];
#pragma unroll
            for (int j = 0; j < TN; j++) b[j] = Bs[kk][tx * TN + j];
#pragma unroll
            for (int i = 0; i < TM; i++)
#pragma unroll
                for (int j = 0; j < TN; j++) acc[i][j] += a[i] * b[j];
        }
        __syncthreads();
    }

#pragma unroll
    for (int i = 0; i < TM; i++) {
        int row = bm + ty * TM + i;
        if (row >= M) continue;
#pragma unroll
        for (int j = 0; j < TN; j += 4) {
            int col = bn + tx * TN + j;
            if (col + 3 >= N && col >= N) continue;
            float4 v;
            v.x = acc[i][j + 0];
            v.y = acc[i][j + 1];
            v.z = acc[i][j + 2];
            v.w = acc[i][j + 3];
            if (bias) {
                v.x += bias[col + 0];
                v.y += bias[col + 1];
                v.z += bias[col + 2];
                v.w += bias[col + 3];
            }
            *(float4*)&C[(size_t)row * N + col] = v;
        }
    }
}

// ---------------------------------------------------------------------------
// Local attention: one block per (b, h, group). 196 queries x 197 keys x 64.
// K/V staged in dynamic smem; thread-per-query, two-pass online softmax with
// score recompute (no spilled score arrays).
// ---------------------------------------------------------------------------
__global__ __launch_bounds__(256, 1)
void local_attn_kernel(const float* __restrict__ qkv, float* __restrict__ out) {
    extern __shared__ float sh[];
    float* Ks = sh;                 // [197][64]
    float* Vs = sh + NK_ * DH_;     // [197][64]

    const int blk = blockIdx.x;
    const int b = blk / (H_ * F_);
    const int rem = blk % (H_ * F_);
    const int h = rem / F_;
    const int fi = rem % F_;
    const int t0 = 1 + fi * NP_;
    const int tid = threadIdx.x;

    const size_t bbase = (size_t)b * NTOT * QKVC;
    const int hoff = h * DH_;

    // cooperative load K,V (float4 granularity)
    for (int idx = tid; idx < NK_ * (DH_ / 4); idx += blockDim.x) {
        int j = idx >> 4;           // key row
        int d4 = idx & 15;          // float4 index
        int tok = (j == 0) ? 0 : (t0 + j - 1);
        const float* kp = qkv + bbase + (size_t)tok * QKVC + DIM_ + hoff + d4 * 4;
        *(float4*)&Ks[j * DH_ + d4 * 4] = *(const float4*)kp;
        *(float4*)&Vs[j * DH_ + d4 * 4] = *(const float4*)(kp + DIM_);
    }
    __syncthreads();

    const int qi = tid;
    if (qi >= NP_) return;
    const int qtok = t0 + qi;
    const float scale = 0.125f;     // 64^-0.5

    const float* qp = qkv + bbase + (size_t)qtok * QKVC + hoff;
    float4 q[16];
#pragma unroll
    for (int i = 0; i < 16; i++) {
        float4 t = *(const float4*)&qp[i * 4];
        q[i].x = t.x * scale; q[i].y = t.y * scale;
        q[i].z = t.z * scale; q[i].w = t.w * scale;
    }

    // pass 1: running max + sumexp
    float m = -1e30f, l = 0.0f;
    for (int j = 0; j < NK_; j++) {
        float s = 0.0f;
#pragma unroll
        for (int i = 0; i < 16; i++) {
            float4 kk = *(const float4*)&Ks[j * DH_ + i * 4];
            s += q[i].x * kk.x + q[i].y * kk.y + q[i].z * kk.z + q[i].w * kk.w;
        }
        float mn = fmaxf(m, s);
        l = l * __expf(m - mn) + __expf(s - mn);
        m = mn;
    }

    // pass 2: recompute scores, accumulate p * V
    float4 acc[16];
#pragma unroll
    for (int i = 0; i < 16; i++) acc[i] = make_float4(0.f, 0.f, 0.f, 0.f);

    for (int j = 0; j < NK_; j++) {
        float s = 0.0f;
#pragma unroll
        for (int i = 0; i < 16; i++) {
            float4 kk = *(const float4*)&Ks[j * DH_ + i * 4];
            s += q[i].x * kk.x + q[i].y * kk.y + q[i].z * kk.z + q[i].w * kk.w;
        }
        float p = __expf(s - m);
#pragma unroll
        for (int i = 0; i < 16; i++) {
            float4 vv = *(const float4*)&Vs[j * DH_ + i * 4];
            acc[i].x += p * vv.x; acc[i].y += p * vv.y;
            acc[i].z += p * vv.z; acc[i].w += p * vv.w;
        }
    }

    const float inv = 1.0f / l;
    float* op = out + ((size_t)b * NTOT + qtok) * DIM_ + hoff;
#pragma unroll
    for (int i = 0; i < 16; i++) {
        float4 v;
        v.x = acc[i].x * inv; v.y = acc[i].y * inv;
        v.z = acc[i].z * inv; v.w = acc[i].w * inv;
        *(float4*)&op[i * 4] = v;
    }
}

// ---------------------------------------------------------------------------
// CLS attention: one block per (b,h); q[token 0] attends over all 3137 keys.
// ---------------------------------------------------------------------------
__global__ __launch_bounds__(256)
void cls_attn_kernel(const float* __restrict__ qkv, float* __restrict__ out) {
    __shared__ float qs[DH_];
    __shared__ float sc[NTOT];
    __shared__ float redbuf[8];
    __shared__ float accs[4][DH_];

    const int b = blockIdx.x / H_;
    const int h = blockIdx.x % H_;
    const int tid = threadIdx.x;
    const int lane = tid & 31;
    const int warp = tid >> 5;
    const size_t bbase = (size_t)b * NTOT * QKVC;
    const int hoff = h * DH_;

    if (tid < DH_) qs[tid] = qkv[bbase + hoff + tid] * 0.125f;
    __syncthreads();

    // pass 1: scores + max
    float lmax = -1e30f;
    for (int j = tid; j < NTOT; j += 256) {
        const float* kp = qkv + bbase + (size_t)j * QKVC + DIM_ + hoff;
        float s = 0.0f;
#pragma unroll
        for (int i = 0; i < 16; i++) {
            float4 kk = *(const float4*)&kp[i * 4];
            float4 qq = *(const float4*)&qs[i * 4];
            s += qq.x * kk.x + qq.y * kk.y + qq.z * kk.z + qq.w * kk.w;
        }
        sc[j] = s;
        lmax = fmaxf(lmax, s);
    }
#pragma unroll
    for (int o = 16; o; o >>= 1) lmax = fmaxf(lmax, __shfl_xor_sync(~0u, lmax, o));
    if (lane == 0) redbuf[warp] = lmax;
    __syncthreads();
    float m = fmaxf(fmaxf(fmaxf(redbuf[0], redbuf[1]), fmaxf(redbuf[2], redbuf[3])),
                    fmaxf(fmaxf(redbuf[4], redbuf[5]), fmaxf(redbuf[6], redbuf[7])));
    __syncthreads();

    // pass 2: exp + sum
    float lsum = 0.0f;
    for (int j = tid; j < NTOT; j += 256) {
        float p = __expf(sc[j] - m);
        sc[j] = p;
        lsum += p;
    }
#pragma unroll
    for (int o = 16; o; o >>= 1) lsum += __shfl_xor_sync(~0u, lsum, o);
    if (lane == 0) redbuf[warp] = lsum;
    __syncthreads();
    float l = redbuf[0] + redbuf[1] + redbuf[2] + redbuf[3] +
              redbuf[4] + redbuf[5] + redbuf[6] + redbuf[7];

    // pass 3: out[d] = sum_j p_j * v[j][d]
    const int d = tid & 63;
    const int g = tid >> 6;     // 4 groups
    float acc = 0.0f;
    for (int j = g; j < NTOT; j += 4)
        acc += sc[j] * qkv[bbase + (size_t)j * QKVC + 2 * DIM_ + hoff + d];
    accs[g][d] = acc;
    __syncthreads();
    if (tid < DH_) {
        float o = (accs[0][tid] + accs[1][tid] + accs[2][tid] + accs[3][tid]) / l;
        out[((size_t)b * NTOT) * DIM_ + hoff + tid] = o;
    }
}

// ---------------------------------------------------------------------------
extern "C" void kernel_launch(void* const* d_in, const int* in_sizes, int n_in,
                              void* d_out, int out_size) {
    const float* x    = (const float*)d_in[0];
    const float* Wqkv = (const float*)d_in[1];
    const float* Wout = (const float*)d_in[2];
    const float* bout = (const float*)d_in[3];
    float* out = (float*)d_out;

    float* qkv = nullptr;
    float* att = nullptr;
    cudaGetSymbolAddress((void**)&qkv, g_qkv);
    cudaGetSymbolAddress((void**)&att, g_att);

    // 1) qkv = x @ W_qkv   [12548 x 1536]
    {
        dim3 grid(QKVC / BN, (MROWS + BM - 1) / BM);
        sgemm_kernel<<<grid, 256>>>(x, Wqkv, nullptr, qkv, MROWS, QKVC, DIM_);
    }

    // 2) local attention (512 blocks), dynamic smem for K+V tiles
    {
        int smem = 2 * NK_ * DH_ * (int)sizeof(float);  // 100,864 B
        cudaFuncSetAttribute(local_attn_kernel,
                             cudaFuncAttributeMaxDynamicSharedMemorySize, smem);
        local_attn_kernel<<<B_ * H_ * F_, 256, smem>>>(qkv, att);
    }

    // 3) cls attention (32 blocks)
    cls_attn_kernel<<<B_ * H_, 256>>>(qkv, att);

    // 4) out = att @ W_out + b_out   [12548 x 512]
    {
        dim3 grid(DIM_ / BN, (MROWS + BM - 1) / BM);
        sgemm_kernel<<<grid, 256>>>(att, Wout, bout, out, MROWS, DIM_, DIM_);
    }
}

// round 6
// speedup vs baseline: 1.4256x; 1.4256x over previous
#include <cuda_runtime.h>
#include <cuda_bf16.h>
#include <cstdint>

// Problem constants
#define B_   4
#define F_   16
#define NP_  196
#define DIM_ 512
#define H_   8
#define DH_  64
#define NTOT 3137            // 1 + F*NP
#define MROWS (B_ * NTOT)    // 12548
#define MPAD  12672          // 99 * 128
#define QKVC (3 * H_ * DH_)  // 1536
#define NK_  197             // cls + 196 local keys
#define KP   1536            // split-bf16 K' = 3*512

// ---------------------------------------------------------------------------
// Scratch (allocation-free: __device__ globals). A-matrices padded to MPAD rows
// so the GEMM never reads out of bounds (pad rows are zero / junk, and the
// corresponding C rows are predicated off).
// ---------------------------------------------------------------------------
__device__ float         g_qkv[(size_t)MROWS * QKVC];        // fp32 qkv (~77MB)
__device__ __nv_bfloat16 g_A2x[(size_t)MPAD * KP];           // x split-bf16
__device__ __nv_bfloat16 g_A2att[(size_t)MPAD * KP];         // attn out split-bf16
__device__ __nv_bfloat16 g_B2qkv[(size_t)QKVC * KP];         // W_qkv^T split-bf16
__device__ __nv_bfloat16 g_B2out[(size_t)DIM_ * KP];         // W_out^T split-bf16

// ---------------------------------------------------------------------------
__device__ __forceinline__ uint32_t smem_to_u32(const void* p) {
    uint32_t a;
    asm("{ .reg .u64 t; cvta.to.shared.u64 t, %1; cvt.u32.u64 %0, t; }"
        : "=r"(a) : "l"(p));
    return a;
}

// split helpers
__device__ __forceinline__ void split_bf16(float v, __nv_bfloat16& h, __nv_bfloat16& l) {
    h = __float2bfloat16_rn(v);
    l = __float2bfloat16_rn(v - __bfloat162float(h));
}
__device__ __forceinline__ uint32_t pack2(__nv_bfloat16 a, __nv_bfloat16 b) {
    __nv_bfloat162 t = __halves2bfloat162(a, b);
    return *(uint32_t*)&t;
}

// ---------------------------------------------------------------------------
// HMMA GEMM: C[M,N] = A2[M,KP] . B2[N,KP]^T (+ bias).
// 128x128 CTA tile, BK=32, 256 threads (8 warps, each 32Mx64N),
// cp.async double-buffered smem, ldmatrix + mma.sync m16n8k16 bf16.
// Swizzle: phys_seg = seg ^ (row & 3) on 16B segments of 64B rows.
// ---------------------------------------------------------------------------
#define GBM 128
#define GBN 128
#define GBK 32
#define KITERS (KP / GBK)    // 48

__global__ __launch_bounds__(256, 1)
void gemm_mma(const __nv_bfloat16* __restrict__ A2,
              const __nv_bfloat16* __restrict__ B2,
              const float* __restrict__ bias,
              float* __restrict__ C, int M, int N) {
    __shared__ __align__(128) unsigned char sA[2][GBM * GBK * 2];  // 2 x 8KB
    __shared__ __align__(128) unsigned char sB[2][GBN * GBK * 2];  // 2 x 8KB

    const int tid  = threadIdx.x;
    const int wid  = tid >> 5;
    const int lane = tid & 31;
    const int wm = (wid & 3) * 32;        // warp M offset in tile
    const int wn = (wid >> 2) * 64;       // warp N offset in tile
    const int tm = blockIdx.y * GBM;
    const int tn = blockIdx.x * GBN;

    const uint32_t sAu = smem_to_u32(sA);
    const uint32_t sBu = smem_to_u32(sB);

    // global->smem: each thread copies 2x16B for A and 2x16B for B per tile.
    const int lrow = tid >> 1;            // 0..127
    const int lseg = (tid & 1) * 2;       // 0 or 2
    const __nv_bfloat16* gA = A2 + (size_t)(tm + lrow) * KP + lseg * 8;
    const __nv_bfloat16* gB = B2 + (size_t)(tn + lrow) * KP + lseg * 8;
    uint32_t dA0 = sAu + lrow * 64 + (((lseg + 0) ^ (lrow & 3)) * 16);
    uint32_t dA1 = sAu + lrow * 64 + (((lseg + 1) ^ (lrow & 3)) * 16);
    uint32_t dB0 = sBu + lrow * 64 + (((lseg + 0) ^ (lrow & 3)) * 16);
    uint32_t dB1 = sBu + lrow * 64 + (((lseg + 1) ^ (lrow & 3)) * 16);

#define ISSUE_LOADS(it, buf) do {                                              \
    int _k0 = (it) * GBK;                                                      \
    uint32_t _bo = (buf) * (GBM * GBK * 2);                                    \
    asm volatile("cp.async.cg.shared.global [%0], [%1], 16;"                   \
                 :: "r"(dA0 + _bo), "l"(gA + _k0));                            \
    asm volatile("cp.async.cg.shared.global [%0], [%1], 16;"                   \
                 :: "r"(dA1 + _bo), "l"(gA + _k0 + 8));                        \
    asm volatile("cp.async.cg.shared.global [%0], [%1], 16;"                   \
                 :: "r"(dB0 + _bo), "l"(gB + _k0));                            \
    asm volatile("cp.async.cg.shared.global [%0], [%1], 16;"                   \
                 :: "r"(dB1 + _bo), "l"(gB + _k0 + 8));                        \
    asm volatile("cp.async.commit_group;");                                    \
} while (0)

    float acc[2][8][4];
#pragma unroll
    for (int i = 0; i < 2; i++)
#pragma unroll
        for (int j = 0; j < 8; j++)
#pragma unroll
            for (int r = 0; r < 4; r++) acc[i][j][r] = 0.0f;

    // precomputed ldmatrix row indices (per lane)
    const int rA0 = wm + (lane & 15);          // m-tile 0 rows
    const int rA1 = wm + 16 + (lane & 15);     // m-tile 1 rows
    const int kh  = lane >> 4;                 // k-half

    ISSUE_LOADS(0, 0);

    for (int it = 0; it < KITERS; ++it) {
        const int buf = it & 1;
        if (it + 1 < KITERS) {
            ISSUE_LOADS(it + 1, buf ^ 1);
            asm volatile("cp.async.wait_group 1;");
        } else {
            asm volatile("cp.async.wait_group 0;");
        }
        __syncthreads();

        const uint32_t aB = sAu + buf * (GBM * GBK * 2);
        const uint32_t bB = sBu + buf * (GBN * GBK * 2);

#pragma unroll
        for (int kk = 0; kk < 2; kk++) {
            const int segl = kk * 2 + kh;
            uint32_t a[2][4];
            {
                uint32_t ad0 = aB + rA0 * 64 + ((segl ^ (rA0 & 3)) * 16);
                asm volatile("ldmatrix.sync.aligned.m8n8.x4.shared.b16 {%0,%1,%2,%3}, [%4];"
                             : "=r"(a[0][0]), "=r"(a[0][1]), "=r"(a[0][2]), "=r"(a[0][3])
                             : "r"(ad0));
                uint32_t ad1 = aB + rA1 * 64 + ((segl ^ (rA1 & 3)) * 16);
                asm volatile("ldmatrix.sync.aligned.m8n8.x4.shared.b16 {%0,%1,%2,%3}, [%4];"
                             : "=r"(a[1][0]), "=r"(a[1][1]), "=r"(a[1][2]), "=r"(a[1][3])
                             : "r"(ad1));
            }
            uint32_t b[4][4];
#pragma unroll
            for (int j2 = 0; j2 < 4; j2++) {
                int rB = wn + j2 * 16 + (lane & 15);
                uint32_t bd = bB + rB * 64 + ((segl ^ (rB & 3)) * 16);
                asm volatile("ldmatrix.sync.aligned.m8n8.x4.shared.b16 {%0,%1,%2,%3}, [%4];"
                             : "=r"(b[j2][0]), "=r"(b[j2][1]), "=r"(b[j2][2]), "=r"(b[j2][3])
                             : "r"(bd));
            }
#pragma unroll
            for (int i = 0; i < 2; i++)
#pragma unroll
                for (int j = 0; j < 8; j++) {
                    uint32_t b0 = b[j >> 1][(j & 1)];
                    uint32_t b1 = b[j >> 1][(j & 1) + 2];
                    asm volatile(
                        "mma.sync.aligned.m16n8k16.row.col.f32.bf16.bf16.f32 "
                        "{%0,%1,%2,%3}, {%4,%5,%6,%7}, {%8,%9}, {%0,%1,%2,%3};"
                        : "+f"(acc[i][j][0]), "+f"(acc[i][j][1]),
                          "+f"(acc[i][j][2]), "+f"(acc[i][j][3])
                        : "r"(a[i][0]), "r"(a[i][1]), "r"(a[i][2]), "r"(a[i][3]),
                          "r"(b0), "r"(b1));
                }
        }
        __syncthreads();
    }

    // epilogue: direct float2 stores (predicated on M)
#pragma unroll
    for (int i = 0; i < 2; i++) {
        int row0 = tm + wm + i * 16 + (lane >> 2);
#pragma unroll
        for (int half = 0; half < 2; half++) {
            int row = row0 + half * 8;
            if (row >= M) continue;
#pragma unroll
            for (int j = 0; j < 8; j++) {
                int col = tn + wn + j * 8 + (lane & 3) * 2;
                float2 v;
                v.x = acc[i][j][half * 2 + 0];
                v.y = acc[i][j][half * 2 + 1];
                if (bias) {
                    float2 bb = *(const float2*)(bias + col);
                    v.x += bb.x; v.y += bb.y;
                }
                *(float2*)(C + (size_t)row * N + col) = v;
            }
        }
    }
}

// ---------------------------------------------------------------------------
// conv_x: x fp32 [M,512] -> A2 split-bf16 [M,1536]  (hi | lo | hi)
// ---------------------------------------------------------------------------
__global__ __launch_bounds__(256)
void conv_x_kernel(const float* __restrict__ x, __nv_bfloat16* __restrict__ A2) {
    size_t i = (size_t)blockIdx.x * blockDim.x + threadIdx.x;   // one float4
    if (i >= (size_t)MROWS * 128) return;
    size_t row = i >> 7;
    int c4 = (int)(i & 127);
    float4 v = *(const float4*)(x + row * 512 + c4 * 4);
    __nv_bfloat16 h0, h1, h2, h3, l0, l1, l2, l3;
    split_bf16(v.x, h0, l0); split_bf16(v.y, h1, l1);
    split_bf16(v.z, h2, l2); split_bf16(v.w, h3, l3);
    uint2 hp = make_uint2(pack2(h0, h1), pack2(h2, h3));
    uint2 lp = make_uint2(pack2(l0, l1), pack2(l2, l3));
    __nv_bfloat16* base = A2 + row * KP + c4 * 4;
    *(uint2*)(base)        = hp;
    *(uint2*)(base + 512)  = lp;
    *(uint2*)(base + 1024) = hp;
}

// ---------------------------------------------------------------------------
// convW: W fp32 [512,N] -> B2 split-bf16 [N,1536] (transposed, hi | hi | lo)
// ---------------------------------------------------------------------------
__global__ __launch_bounds__(1024)
void convW_kernel(const float* __restrict__ W, __nv_bfloat16* __restrict__ B2, int N) {
    __shared__ float t[32][33];
    int n0 = blockIdx.x * 32, k0 = blockIdx.y * 32;
    int tx = threadIdx.x, ty = threadIdx.y;
    t[ty][tx] = W[(size_t)(k0 + ty) * N + n0 + tx];
    __syncthreads();
    int n = n0 + ty, k = k0 + tx;
    float v = t[tx][ty];
    __nv_bfloat16 h, l;
    split_bf16(v, h, l);
    size_t base = (size_t)n * KP + k;
    B2[base]        = h;
    B2[base + 512]  = h;
    B2[base + 1024] = l;
}

// ---------------------------------------------------------------------------
// Local attention: one block per (b, h, group). Writes split-bf16 directly.
// ---------------------------------------------------------------------------
__global__ __launch_bounds__(256, 1)
void local_attn_kernel(const float* __restrict__ qkv, __nv_bfloat16* __restrict__ A2) {
    extern __shared__ float sh[];
    float* Ks = sh;
    float* Vs = sh + NK_ * DH_;

    const int blk = blockIdx.x;
    const int b = blk / (H_ * F_);
    const int rem = blk % (H_ * F_);
    const int h = rem / F_;
    const int fi = rem % F_;
    const int t0 = 1 + fi * NP_;
    const int tid = threadIdx.x;

    const size_t bbase = (size_t)b * NTOT * QKVC;
    const int hoff = h * DH_;

    for (int idx = tid; idx < NK_ * (DH_ / 4); idx += blockDim.x) {
        int j = idx >> 4;
        int d4 = idx & 15;
        int tok = (j == 0) ? 0 : (t0 + j - 1);
        const float* kp = qkv + bbase + (size_t)tok * QKVC + DIM_ + hoff + d4 * 4;
        *(float4*)&Ks[j * DH_ + d4 * 4] = *(const float4*)kp;
        *(float4*)&Vs[j * DH_ + d4 * 4] = *(const float4*)(kp + DIM_);
    }
    __syncthreads();

    const int qi = tid;
    if (qi >= NP_) return;
    const int qtok = t0 + qi;
    const float scale = 0.125f;

    const float* qp = qkv + bbase + (size_t)qtok * QKVC + hoff;
    float4 q[16];
#pragma unroll
    for (int i = 0; i < 16; i++) {
        float4 t = *(const float4*)&qp[i * 4];
        q[i].x = t.x * scale; q[i].y = t.y * scale;
        q[i].z = t.z * scale; q[i].w = t.w * scale;
    }

    float m = -1e30f, l = 0.0f;
    for (int j = 0; j < NK_; j++) {
        float s = 0.0f;
#pragma unroll
        for (int i = 0; i < 16; i++) {
            float4 kk = *(const float4*)&Ks[j * DH_ + i * 4];
            s += q[i].x * kk.x + q[i].y * kk.y + q[i].z * kk.z + q[i].w * kk.w;
        }
        float mn = fmaxf(m, s);
        l = l * __expf(m - mn) + __expf(s - mn);
        m = mn;
    }

    float4 acc[16];
#pragma unroll
    for (int i = 0; i < 16; i++) acc[i] = make_float4(0.f, 0.f, 0.f, 0.f);

    for (int j = 0; j < NK_; j++) {
        float s = 0.0f;
#pragma unroll
        for (int i = 0; i < 16; i++) {
            float4 kk = *(const float4*)&Ks[j * DH_ + i * 4];
            s += q[i].x * kk.x + q[i].y * kk.y + q[i].z * kk.z + q[i].w * kk.w;
        }
        float p = __expf(s - m);
#pragma unroll
        for (int i = 0; i < 16; i++) {
            float4 vv = *(const float4*)&Vs[j * DH_ + i * 4];
            acc[i].x += p * vv.x; acc[i].y += p * vv.y;
            acc[i].z += p * vv.z; acc[i].w += p * vv.w;
        }
    }

    const float inv = 1.0f / l;
    __nv_bfloat16* base = A2 + ((size_t)b * NTOT + qtok) * KP + hoff;
#pragma unroll
    for (int i = 0; i < 16; i++) {
        float v0 = acc[i].x * inv, v1 = acc[i].y * inv;
        float v2 = acc[i].z * inv, v3 = acc[i].w * inv;
        __nv_bfloat16 h0, h1, h2, h3, l0, l1, l2, l3;
        split_bf16(v0, h0, l0); split_bf16(v1, h1, l1);
        split_bf16(v2, h2, l2); split_bf16(v3, h3, l3);
        uint2 hp = make_uint2(pack2(h0, h1), pack2(h2, h3));
        uint2 lp = make_uint2(pack2(l0, l1), pack2(l2, l3));
        *(uint2*)(base + i * 4)        = hp;
        *(uint2*)(base + 512 + i * 4)  = lp;
        *(uint2*)(base + 1024 + i * 4) = hp;
    }
}

// ---------------------------------------------------------------------------
// CLS attention: one block per (b,h). Writes split-bf16 directly.
// ---------------------------------------------------------------------------
__global__ __launch_bounds__(256)
void cls_attn_kernel(const float* __restrict__ qkv, __nv_bfloat16* __restrict__ A2) {
    __shared__ float qs[DH_];
    __shared__ float sc[NTOT];
    __shared__ float redbuf[8];
    __shared__ float accs[4][DH_];

    const int b = blockIdx.x / H_;
    const int h = blockIdx.x % H_;
    const int tid = threadIdx.x;
    const int lane = tid & 31;
    const int warp = tid >> 5;
    const size_t bbase = (size_t)b * NTOT * QKVC;
    const int hoff = h * DH_;

    if (tid < DH_) qs[tid] = qkv[bbase + hoff + tid] * 0.125f;
    __syncthreads();

    float lmax = -1e30f;
    for (int j = tid; j < NTOT; j += 256) {
        const float* kp = qkv + bbase + (size_t)j * QKVC + DIM_ + hoff;
        float s = 0.0f;
#pragma unroll
        for (int i = 0; i < 16; i++) {
            float4 kk = *(const float4*)&kp[i * 4];
            float4 qq = *(const float4*)&qs[i * 4];
            s += qq.x * kk.x + qq.y * kk.y + qq.z * kk.z + qq.w * kk.w;
        }
        sc[j] = s;
        lmax = fmaxf(lmax, s);
    }
#pragma unroll
    for (int o = 16; o; o >>= 1) lmax = fmaxf(lmax, __shfl_xor_sync(~0u, lmax, o));
    if (lane == 0) redbuf[warp] = lmax;
    __syncthreads();
    float m = fmaxf(fmaxf(fmaxf(redbuf[0], redbuf[1]), fmaxf(redbuf[2], redbuf[3])),
                    fmaxf(fmaxf(redbuf[4], redbuf[5]), fmaxf(redbuf[6], redbuf[7])));
    __syncthreads();

    float lsum = 0.0f;
    for (int j = tid; j < NTOT; j += 256) {
        float p = __expf(sc[j] - m);
        sc[j] = p;
        lsum += p;
    }
#pragma unroll
    for (int o = 16; o; o >>= 1) lsum += __shfl_xor_sync(~0u, lsum, o);
    if (lane == 0) redbuf[warp] = lsum;
    __syncthreads();
    float l = redbuf[0] + redbuf[1] + redbuf[2] + redbuf[3] +
              redbuf[4] + redbuf[5] + redbuf[6] + redbuf[7];

    const int d = tid & 63;
    const int g = tid >> 6;
    float acc = 0.0f;
    for (int j = g; j < NTOT; j += 4)
        acc += sc[j] * qkv[bbase + (size_t)j * QKVC + 2 * DIM_ + hoff + d];
    accs[g][d] = acc;
    __syncthreads();
    if (tid < DH_) {
        float o = (accs[0][tid] + accs[1][tid] + accs[2][tid] + accs[3][tid]) / l;
        __nv_bfloat16 hh, ll;
        split_bf16(o, hh, ll);
        __nv_bfloat16* base = A2 + (size_t)b * NTOT * KP + hoff + tid;
        base[0]    = hh;
        base[512]  = ll;
        base[1024] = hh;
    }
}

// ---------------------------------------------------------------------------
extern "C" void kernel_launch(void* const* d_in, const int* in_sizes, int n_in,
                              void* d_out, int out_size) {
    const float* x    = (const float*)d_in[0];
    const float* Wqkv = (const float*)d_in[1];
    const float* Wout = (const float*)d_in[2];
    const float* bout = (const float*)d_in[3];
    float* out = (float*)d_out;

    float* qkv = nullptr;
    __nv_bfloat16 *A2x = nullptr, *A2att = nullptr, *B2qkv = nullptr, *B2out = nullptr;
    cudaGetSymbolAddress((void**)&qkv, g_qkv);
    cudaGetSymbolAddress((void**)&A2x, g_A2x);
    cudaGetSymbolAddress((void**)&A2att, g_A2att);
    cudaGetSymbolAddress((void**)&B2qkv, g_B2qkv);
    cudaGetSymbolAddress((void**)&B2out, g_B2out);

    // conversions
    {
        size_t tot = (size_t)MROWS * 128;
        conv_x_kernel<<<(unsigned)((tot + 255) / 256), 256>>>(x, A2x);
        convW_kernel<<<dim3(QKVC / 32, DIM_ / 32), dim3(32, 32)>>>(Wqkv, B2qkv, QKVC);
        convW_kernel<<<dim3(DIM_ / 32, DIM_ / 32), dim3(32, 32)>>>(Wout, B2out, DIM_);
    }

    // 1) qkv = x @ W_qkv  (HMMA split-bf16) -> fp32
    gemm_mma<<<dim3(QKVC / GBN, MPAD / GBM), 256>>>(A2x, B2qkv, nullptr, qkv,
                                                    MROWS, QKVC);

    // 2) local attention (512 blocks)
    {
        int smem = 2 * NK_ * DH_ * (int)sizeof(float);
        cudaFuncSetAttribute(local_attn_kernel,
                             cudaFuncAttributeMaxDynamicSharedMemorySize, smem);
        local_attn_kernel<<<B_ * H_ * F_, 256, smem>>>(qkv, A2att);
    }

    // 3) cls attention
    cls_attn_kernel<<<B_ * H_, 256>>>(qkv, A2att);

    // 4) out = att @ W_out + b_out
    gemm_mma<<<dim3(DIM_ / GBN, MPAD / GBM), 256>>>(A2att, B2out, bout, out,
                                                    MROWS, DIM_);
}

// round 8
// speedup vs baseline: 1.7445x; 1.2237x over previous
#include <cuda_runtime.h>
#include <cuda_bf16.h>
#include <cstdint>

// Problem constants
#define B_   4
#define F_   16
#define NP_  196
#define DIM_ 512
#define H_   8
#define DH_  64
#define NTOT 3137            // 1 + F*NP
#define MROWS (B_ * NTOT)    // 12548
#define MPAD  12672          // 99 * 128
#define QKVC (3 * H_ * DH_)  // 1536
#define NK_  197             // cls + 196 local keys
#define KP   1536            // split-bf16 K' = 3*512

// ---------------------------------------------------------------------------
// Scratch (allocation-free: __device__ globals)
// ---------------------------------------------------------------------------
__device__ float         g_qkv[(size_t)MROWS * QKVC];        // fp32 qkv (~77MB)
__device__ __nv_bfloat16 g_A2x[(size_t)MPAD * KP];           // x split-bf16
__device__ __nv_bfloat16 g_A2att[(size_t)MPAD * KP];         // attn out split-bf16
__device__ __nv_bfloat16 g_B2qkv[(size_t)QKVC * KP];         // W_qkv^T split-bf16
__device__ __nv_bfloat16 g_B2out[(size_t)DIM_ * KP];         // W_out^T split-bf16

// ---------------------------------------------------------------------------
__device__ __forceinline__ uint32_t smem_to_u32(const void* p) {
    uint32_t a;
    asm("{ .reg .u64 t; cvta.to.shared.u64 t, %1; cvt.u32.u64 %0, t; }"
        : "=r"(a) : "l"(p));
    return a;
}

// split helpers
__device__ __forceinline__ void split_bf16(float v, __nv_bfloat16& h, __nv_bfloat16& l) {
    h = __float2bfloat16_rn(v);
    l = __float2bfloat16_rn(v - __bfloat162float(h));
}
__device__ __forceinline__ uint32_t pack2(__nv_bfloat16 a, __nv_bfloat16 b) {
    __nv_bfloat162 t = __halves2bfloat162(a, b);
    return *(uint32_t*)&t;
}

// packed f32x2 helpers (sm_100+)
__device__ __forceinline__ unsigned long long ffma2(unsigned long long a,
                                                    unsigned long long b,
                                                    unsigned long long c) {
    unsigned long long d;
    asm("fma.rn.f32x2 %0, %1, %2, %3;" : "=l"(d) : "l"(a), "l"(b), "l"(c));
    return d;
}
__device__ __forceinline__ unsigned long long packf2(float x, float y) {
    unsigned long long r;
    asm("mov.b64 %0, {%1, %2};" : "=l"(r) : "f"(x), "f"(y));
    return r;
}
__device__ __forceinline__ void unpackf2(unsigned long long r, float& x, float& y) {
    asm("mov.b64 {%0, %1}, %2;" : "=f"(x), "=f"(y) : "l"(r));
}

// ---------------------------------------------------------------------------
// HMMA GEMM: C[M,N] = A2[M,KP] . B2[N,KP]^T (+ bias).
// 128x128 CTA tile, BK=32, 256 threads (8 warps, each 32Mx64N),
// cp.async double-buffered smem, ldmatrix + mma.sync m16n8k16 bf16.
// ---------------------------------------------------------------------------
#define GBM 128
#define GBN 128
#define GBK 32
#define KITERS (KP / GBK)    // 48

__global__ __launch_bounds__(256, 2)
void gemm_mma(const __nv_bfloat16* __restrict__ A2,
              const __nv_bfloat16* __restrict__ B2,
              const float* __restrict__ bias,
              float* __restrict__ C, int M, int N) {
    __shared__ __align__(128) unsigned char sA[2][GBM * GBK * 2];  // 2 x 8KB
    __shared__ __align__(128) unsigned char sB[2][GBN * GBK * 2];  // 2 x 8KB

    const int tid  = threadIdx.x;
    const int wid  = tid >> 5;
    const int lane = tid & 31;
    const int wm = (wid & 3) * 32;        // warp M offset in tile
    const int wn = (wid >> 2) * 64;       // warp N offset in tile
    const int tm = blockIdx.y * GBM;
    const int tn = blockIdx.x * GBN;

    const uint32_t sAu = smem_to_u32(sA);
    const uint32_t sBu = smem_to_u32(sB);

    const int lrow = tid >> 1;            // 0..127
    const int lseg = (tid & 1) * 2;       // 0 or 2
    const __nv_bfloat16* gA = A2 + (size_t)(tm + lrow) * KP + lseg * 8;
    const __nv_bfloat16* gB = B2 + (size_t)(tn + lrow) * KP + lseg * 8;
    uint32_t dA0 = sAu + lrow * 64 + (((lseg + 0) ^ (lrow & 3)) * 16);
    uint32_t dA1 = sAu + lrow * 64 + (((lseg + 1) ^ (lrow & 3)) * 16);
    uint32_t dB0 = sBu + lrow * 64 + (((lseg + 0) ^ (lrow & 3)) * 16);
    uint32_t dB1 = sBu + lrow * 64 + (((lseg + 1) ^ (lrow & 3)) * 16);

#define ISSUE_LOADS(it, buf) do {                                              \
    int _k0 = (it) * GBK;                                                      \
    uint32_t _bo = (buf) * (GBM * GBK * 2);                                    \
    asm volatile("cp.async.cg.shared.global [%0], [%1], 16;"                   \
                 :: "r"(dA0 + _bo), "l"(gA + _k0));                            \
    asm volatile("cp.async.cg.shared.global [%0], [%1], 16;"                   \
                 :: "r"(dA1 + _bo), "l"(gA + _k0 + 8));                        \
    asm volatile("cp.async.cg.shared.global [%0], [%1], 16;"                   \
                 :: "r"(dB0 + _bo), "l"(gB + _k0));                            \
    asm volatile("cp.async.cg.shared.global [%0], [%1], 16;"                   \
                 :: "r"(dB1 + _bo), "l"(gB + _k0 + 8));                        \
    asm volatile("cp.async.commit_group;");                                    \
} while (0)

    float acc[2][8][4];
#pragma unroll
    for (int i = 0; i < 2; i++)
#pragma unroll
        for (int j = 0; j < 8; j++)
#pragma unroll
            for (int r = 0; r < 4; r++) acc[i][j][r] = 0.0f;

    const int rA0 = wm + (lane & 15);
    const int rA1 = wm + 16 + (lane & 15);
    const int kh  = lane >> 4;

    ISSUE_LOADS(0, 0);

    for (int it = 0; it < KITERS; ++it) {
        const int buf = it & 1;
        if (it + 1 < KITERS) {
            ISSUE_LOADS(it + 1, buf ^ 1);
            asm volatile("cp.async.wait_group 1;");
        } else {
            asm volatile("cp.async.wait_group 0;");
        }
        __syncthreads();

        const uint32_t aB = sAu + buf * (GBM * GBK * 2);
        const uint32_t bB = sBu + buf * (GBN * GBK * 2);

#pragma unroll
        for (int kk = 0; kk < 2; kk++) {
            const int segl = kk * 2 + kh;
            uint32_t a[2][4];
            {
                uint32_t ad0 = aB + rA0 * 64 + ((segl ^ (rA0 & 3)) * 16);
                asm volatile("ldmatrix.sync.aligned.m8n8.x4.shared.b16 {%0,%1,%2,%3}, [%4];"
                             : "=r"(a[0][0]), "=r"(a[0][1]), "=r"(a[0][2]), "=r"(a[0][3])
                             : "r"(ad0));
                uint32_t ad1 = aB + rA1 * 64 + ((segl ^ (rA1 & 3)) * 16);
                asm volatile("ldmatrix.sync.aligned.m8n8.x4.shared.b16 {%0,%1,%2,%3}, [%4];"
                             : "=r"(a[1][0]), "=r"(a[1][1]), "=r"(a[1][2]), "=r"(a[1][3])
                             : "r"(ad1));
            }
            uint32_t b[4][4];
#pragma unroll
            for (int j2 = 0; j2 < 4; j2++) {
                int rB = wn + j2 * 16 + (lane & 15);
                uint32_t bd = bB + rB * 64 + ((segl ^ (rB & 3)) * 16);
                asm volatile("ldmatrix.sync.aligned.m8n8.x4.shared.b16 {%0,%1,%2,%3}, [%4];"
                             : "=r"(b[j2][0]), "=r"(b[j2][1]), "=r"(b[j2][2]), "=r"(b[j2][3])
                             : "r"(bd));
            }
#pragma unroll
            for (int i = 0; i < 2; i++)
#pragma unroll
                for (int j = 0; j < 8; j++) {
                    uint32_t b0 = b[j >> 1][(j & 1)];
                    uint32_t b1 = b[j >> 1][(j & 1) + 2];
                    asm volatile(
                        "mma.sync.aligned.m16n8k16.row.col.f32.bf16.bf16.f32 "
                        "{%0,%1,%2,%3}, {%4,%5,%6,%7}, {%8,%9}, {%0,%1,%2,%3};"
                        : "+f"(acc[i][j][0]), "+f"(acc[i][j][1]),
                          "+f"(acc[i][j][2]), "+f"(acc[i][j][3])
                        : "r"(a[i][0]), "r"(a[i][1]), "r"(a[i][2]), "r"(a[i][3]),
                          "r"(b0), "r"(b1));
                }
        }
        __syncthreads();
    }

#pragma unroll
    for (int i = 0; i < 2; i++) {
        int row0 = tm + wm + i * 16 + (lane >> 2);
#pragma unroll
        for (int half = 0; half < 2; half++) {
            int row = row0 + half * 8;
            if (row >= M) continue;
#pragma unroll
            for (int j = 0; j < 8; j++) {
                int col = tn + wn + j * 8 + (lane & 3) * 2;
                float2 v;
                v.x = acc[i][j][half * 2 + 0];
                v.y = acc[i][j][half * 2 + 1];
                if (bias) {
                    float2 bb = *(const float2*)(bias + col);
                    v.x += bb.x; v.y += bb.y;
                }
                *(float2*)(C + (size_t)row * N + col) = v;
            }
        }
    }
}

// ---------------------------------------------------------------------------
// conv_x: x fp32 [M,512] -> A2 split-bf16 [M,1536]  (hi | lo | hi)
// ---------------------------------------------------------------------------
__global__ __launch_bounds__(256)
void conv_x_kernel(const float* __restrict__ x, __nv_bfloat16* __restrict__ A2) {
    size_t i = (size_t)blockIdx.x * blockDim.x + threadIdx.x;
    if (i >= (size_t)MROWS * 128) return;
    size_t row = i >> 7;
    int c4 = (int)(i & 127);
    float4 v = *(const float4*)(x + row * 512 + c4 * 4);
    __nv_bfloat16 h0, h1, h2, h3, l0, l1, l2, l3;
    split_bf16(v.x, h0, l0); split_bf16(v.y, h1, l1);
    split_bf16(v.z, h2, l2); split_bf16(v.w, h3, l3);
    uint2 hp = make_uint2(pack2(h0, h1), pack2(h2, h3));
    uint2 lp = make_uint2(pack2(l0, l1), pack2(l2, l3));
    __nv_bfloat16* base = A2 + row * KP + c4 * 4;
    *(uint2*)(base)        = hp;
    *(uint2*)(base + 512)  = lp;
    *(uint2*)(base + 1024) = hp;
}

// ---------------------------------------------------------------------------
// convW: W fp32 [512,N] -> B2 split-bf16 [N,1536] (transposed, hi | hi | lo)
// ---------------------------------------------------------------------------
__global__ __launch_bounds__(1024)
void convW_kernel(const float* __restrict__ W, __nv_bfloat16* __restrict__ B2, int N) {
    __shared__ float t[32][33];
    int n0 = blockIdx.x * 32, k0 = blockIdx.y * 32;
    int tx = threadIdx.x, ty = threadIdx.y;
    t[ty][tx] = W[(size_t)(k0 + ty) * N + n0 + tx];
    __syncthreads();
    int n = n0 + ty, k = k0 + tx;
    float v = t[tx][ty];
    __nv_bfloat16 h, l;
    split_bf16(v, h, l);
    size_t base = (size_t)n * KP + k;
    B2[base]        = h;
    B2[base + 512]  = h;
    B2[base + 1024] = l;
}

// ---------------------------------------------------------------------------
// Local attention v2: single pass with Cauchy-Schwarz bound as softmax max,
// packed f32x2 FMA for QK dot and PV accumulation.
// ---------------------------------------------------------------------------
__global__ __launch_bounds__(256, 1)
void local_attn_kernel(const float* __restrict__ qkv, __nv_bfloat16* __restrict__ A2) {
    extern __shared__ float sh[];
    float* Ks = sh;                 // [197][64]
    float* Vs = sh + NK_ * DH_;     // [197][64]
    __shared__ int s_maxk2;         // max ||k||^2 as int-ordered float (>=0)

    const int blk = blockIdx.x;
    const int b = blk / (H_ * F_);
    const int rem = blk % (H_ * F_);
    const int h = rem / F_;
    const int fi = rem % F_;
    const int t0 = 1 + fi * NP_;
    const int tid = threadIdx.x;

    const size_t bbase = (size_t)b * NTOT * QKVC;
    const int hoff = h * DH_;

    if (tid == 0) s_maxk2 = 0;
    for (int idx = tid; idx < NK_ * (DH_ / 4); idx += blockDim.x) {
        int j = idx >> 4;
        int d4 = idx & 15;
        int tok = (j == 0) ? 0 : (t0 + j - 1);
        const float* kp = qkv + bbase + (size_t)tok * QKVC + DIM_ + hoff + d4 * 4;
        *(float4*)&Ks[j * DH_ + d4 * 4] = *(const float4*)kp;
        *(float4*)&Vs[j * DH_ + d4 * 4] = *(const float4*)(kp + DIM_);
    }
    __syncthreads();

    // per-row K norms -> block max
    if (tid < NK_) {
        float kn2 = 0.0f;
#pragma unroll
        for (int i = 0; i < 16; i++) {
            float4 kk = *(const float4*)&Ks[tid * DH_ + i * 4];
            kn2 += kk.x * kk.x + kk.y * kk.y + kk.z * kk.z + kk.w * kk.w;
        }
        atomicMax(&s_maxk2, __float_as_int(kn2));
    }
    __syncthreads();
    const float maxk2 = __int_as_float(s_maxk2);

    const int qi = tid;
    if (qi >= NP_) return;
    const int qtok = t0 + qi;
    const float scale = 0.125f;

    const float* qp = qkv + bbase + (size_t)qtok * QKVC + hoff;
    unsigned long long q2[32];
    float qn2 = 0.0f;
#pragma unroll
    for (int i = 0; i < 16; i++) {
        float4 t = *(const float4*)&qp[i * 4];
        float x0 = t.x * scale, x1 = t.y * scale, x2 = t.z * scale, x3 = t.w * scale;
        qn2 += x0 * x0 + x1 * x1 + x2 * x2 + x3 * x3;
        q2[2 * i]     = packf2(x0, x1);
        q2[2 * i + 1] = packf2(x2, x3);
    }
    // Cauchy-Schwarz upper bound on all scores: ||q_scaled|| * max||k||
    const float m = sqrtf(qn2 * maxk2) + 1e-6f;

    unsigned long long acc2[32];
#pragma unroll
    for (int i = 0; i < 32; i++) acc2[i] = 0ULL;
    float l = 0.0f;

    for (int j = 0; j < NK_; j++) {
        const unsigned long long* kr = (const unsigned long long*)&Ks[j * DH_];
        unsigned long long s2a = 0ULL, s2b = 0ULL, s2c = 0ULL, s2d = 0ULL;
#pragma unroll
        for (int i = 0; i < 8; i++) {
            s2a = ffma2(q2[4 * i + 0], kr[4 * i + 0], s2a);
            s2b = ffma2(q2[4 * i + 1], kr[4 * i + 1], s2b);
            s2c = ffma2(q2[4 * i + 2], kr[4 * i + 2], s2c);
            s2d = ffma2(q2[4 * i + 3], kr[4 * i + 3], s2d);
        }
        float a0, a1, b0, b1, c0, c1, d0, d1;
        unpackf2(s2a, a0, a1); unpackf2(s2b, b0, b1);
        unpackf2(s2c, c0, c1); unpackf2(s2d, d0, d1);
        float s = ((a0 + a1) + (b0 + b1)) + ((c0 + c1) + (d0 + d1));
        float p = __expf(s - m);
        l += p;
        unsigned long long p2 = packf2(p, p);
        const unsigned long long* vr = (const unsigned long long*)&Vs[j * DH_];
#pragma unroll
        for (int i = 0; i < 32; i++) acc2[i] = ffma2(p2, vr[i], acc2[i]);
    }

    const float inv = 1.0f / l;
    __nv_bfloat16* base = A2 + ((size_t)b * NTOT + qtok) * KP + hoff;
#pragma unroll
    for (int i = 0; i < 16; i++) {
        float v0, v1, v2, v3;
        unpackf2(acc2[2 * i], v0, v1);
        unpackf2(acc2[2 * i + 1], v2, v3);
        v0 *= inv; v1 *= inv; v2 *= inv; v3 *= inv;
        __nv_bfloat16 h0, h1, h2, h3, l0, l1, l2, l3;
        split_bf16(v0, h0, l0); split_bf16(v1, h1, l1);
        split_bf16(v2, h2, l2); split_bf16(v3, h3, l3);
        uint2 hp = make_uint2(pack2(h0, h1), pack2(h2, h3));
        uint2 lp = make_uint2(pack2(l0, l1), pack2(l2, l3));
        *(uint2*)(base + i * 4)        = hp;
        *(uint2*)(base + 512 + i * 4)  = lp;
        *(uint2*)(base + 1024 + i * 4) = hp;
    }
}

// ---------------------------------------------------------------------------
// CLS attention: one block per (b,h). Writes split-bf16 directly.
// ---------------------------------------------------------------------------
__global__ __launch_bounds__(256)
void cls_attn_kernel(const float* __restrict__ qkv, __nv_bfloat16* __restrict__ A2) {
    __shared__ float qs[DH_];
    __shared__ float sc[NTOT];
    __shared__ float redbuf[8];
    __shared__ float accs[4][DH_];

    const int b = blockIdx.x / H_;
    const int h = blockIdx.x % H_;
    const int tid = threadIdx.x;
    const int lane = tid & 31;
    const int warp = tid >> 5;
    const size_t bbase = (size_t)b * NTOT * QKVC;
    const int hoff = h * DH_;

    if (tid < DH_) qs[tid] = qkv[bbase + hoff + tid] * 0.125f;
    __syncthreads();

    float lmax = -1e30f;
    for (int j = tid; j < NTOT; j += 256) {
        const float* kp = qkv + bbase + (size_t)j * QKVC + DIM_ + hoff;
        float s = 0.0f;
#pragma unroll
        for (int i = 0; i < 16; i++) {
            float4 kk = *(const float4*)&kp[i * 4];
            float4 qq = *(const float4*)&qs[i * 4];
            s += qq.x * kk.x + qq.y * kk.y + qq.z * kk.z + qq.w * kk.w;
        }
        sc[j] = s;
        lmax = fmaxf(lmax, s);
    }
#pragma unroll
    for (int o = 16; o; o >>= 1) lmax = fmaxf(lmax, __shfl_xor_sync(~0u, lmax, o));
    if (lane == 0) redbuf[warp] = lmax;
    __syncthreads();
    float m = fmaxf(fmaxf(fmaxf(redbuf[0], redbuf[1]), fmaxf(redbuf[2], redbuf[3])),
                    fmaxf(fmaxf(redbuf[4], redbuf[5]), fmaxf(redbuf[6], redbuf[7])));
    __syncthreads();

    float lsum = 0.0f;
    for (int j = tid; j < NTOT; j += 256) {
        float p = __expf(sc[j] - m);
        sc[j] = p;
        lsum += p;
    }
#pragma unroll
    for (int o = 16; o; o >>= 1) lsum += __shfl_xor_sync(~0u, lsum, o);
    if (lane == 0) redbuf[warp] = lsum;
    __syncthreads();
    float l = redbuf[0] + redbuf[1] + redbuf[2] + redbuf[3] +
              redbuf[4] + redbuf[5] + redbuf[6] + redbuf[7];

    const int d = tid & 63;
    const int g = tid >> 6;
    float acc = 0.0f;
    for (int j = g; j < NTOT; j += 4)
        acc += sc[j] * qkv[bbase + (size_t)j * QKVC + 2 * DIM_ + hoff + d];
    accs[g][d] = acc;
    __syncthreads();
    if (tid < DH_) {
        float o = (accs[0][tid] + accs[1][tid] + accs[2][tid] + accs[3][tid]) / l;
        __nv_bfloat16 hh, ll;
        split_bf16(o, hh, ll);
        __nv_bfloat16* base = A2 + (size_t)b * NTOT * KP + hoff + tid;
        base[0]    = hh;
        base[512]  = ll;
        base[1024] = hh;
    }
}

// ---------------------------------------------------------------------------
extern "C" void kernel_launch(void* const* d_in, const int* in_sizes, int n_in,
                              void* d_out, int out_size) {
    const float* x    = (const float*)d_in[0];
    const float* Wqkv = (const float*)d_in[1];
    const float* Wout = (const float*)d_in[2];
    const float* bout = (const float*)d_in[3];
    float* out = (float*)d_out;

    float* qkv = nullptr;
    __nv_bfloat16 *A2x = nullptr, *A2att = nullptr, *B2qkv = nullptr, *B2out = nullptr;
    cudaGetSymbolAddress((void**)&qkv, g_qkv);
    cudaGetSymbolAddress((void**)&A2x, g_A2x);
    cudaGetSymbolAddress((void**)&A2att, g_A2att);
    cudaGetSymbolAddress((void**)&B2qkv, g_B2qkv);
    cudaGetSymbolAddress((void**)&B2out, g_B2out);

    // conversions
    {
        size_t tot = (size_t)MROWS * 128;
        conv_x_kernel<<<(unsigned)((tot + 255) / 256), 256>>>(x, A2x);
        convW_kernel<<<dim3(QKVC / 32, DIM_ / 32), dim3(32, 32)>>>(Wqkv, B2qkv, QKVC);
        convW_kernel<<<dim3(DIM_ / 32, DIM_ / 32), dim3(32, 32)>>>(Wout, B2out, DIM_);
    }

    // 1) qkv = x @ W_qkv  (HMMA split-bf16) -> fp32
    gemm_mma<<<dim3(QKVC / GBN, MPAD / GBM), 256>>>(A2x, B2qkv, nullptr, qkv,
                                                    MROWS, QKVC);

    // 2) local attention (512 blocks)
    {
        int smem = 2 * NK_ * DH_ * (int)sizeof(float);
        cudaFuncSetAttribute(local_attn_kernel,
                             cudaFuncAttributeMaxDynamicSharedMemorySize, smem);
        local_attn_kernel<<<B_ * H_ * F_, 256, smem>>>(qkv, A2att);
    }

    // 3) cls attention
    cls_attn_kernel<<<B_ * H_, 256>>>(qkv, A2att);

    // 4) out = att @ W_out + b_out
    gemm_mma<<<dim3(DIM_ / GBN, MPAD / GBM), 256>>>(A2att, B2out, bout, out,
                                                    MROWS, DIM_);
}

// round 10
// speedup vs baseline: 1.8579x; 1.0650x over previous
#include <cuda_runtime.h>
#include <cuda_bf16.h>
#include <cstdint>

// Problem constants
#define B_   4
#define F_   16
#define NP_  196
#define DIM_ 512
#define H_   8
#define DH_  64
#define NTOT 3137            // 1 + F*NP
#define MROWS (B_ * NTOT)    // 12548
#define MPAD  12672          // 99 * 128
#define QKVC (3 * H_ * DH_)  // 1536
#define NK_  197             // cls + 196 local keys
#define KP   1536            // split-bf16 K' = 3*512

// ---------------------------------------------------------------------------
// Scratch (allocation-free: __device__ globals)
// ---------------------------------------------------------------------------
__device__ float         g_qkv[(size_t)MROWS * QKVC];        // fp32 qkv (~77MB)
__device__ __nv_bfloat16 g_A2x[(size_t)MPAD * KP];           // x split-bf16
__device__ __nv_bfloat16 g_A2att[(size_t)MPAD * KP];         // attn out split-bf16
__device__ __nv_bfloat16 g_B2qkv[(size_t)QKVC * KP];         // W_qkv^T split-bf16
__device__ __nv_bfloat16 g_B2out[(size_t)DIM_ * KP];         // W_out^T split-bf16

// ---------------------------------------------------------------------------
__device__ __forceinline__ uint32_t smem_to_u32(const void* p) {
    uint32_t a;
    asm("{ .reg .u64 t; cvta.to.shared.u64 t, %1; cvt.u32.u64 %0, t; }"
        : "=r"(a) : "l"(p));
    return a;
}

// split helpers
__device__ __forceinline__ void split_bf16(float v, __nv_bfloat16& h, __nv_bfloat16& l) {
    h = __float2bfloat16_rn(v);
    l = __float2bfloat16_rn(v - __bfloat162float(h));
}
__device__ __forceinline__ uint32_t pack2(__nv_bfloat16 a, __nv_bfloat16 b) {
    __nv_bfloat162 t = __halves2bfloat162(a, b);
    return *(uint32_t*)&t;
}

// packed f32x2 helpers (sm_100+)
__device__ __forceinline__ unsigned long long ffma2(unsigned long long a,
                                                    unsigned long long b,
                                                    unsigned long long c) {
    unsigned long long d;
    asm("fma.rn.f32x2 %0, %1, %2, %3;" : "=l"(d) : "l"(a), "l"(b), "l"(c));
    return d;
}
__device__ __forceinline__ unsigned long long packf2(float x, float y) {
    unsigned long long r;
    asm("mov.b64 %0, {%1, %2};" : "=l"(r) : "f"(x), "f"(y));
    return r;
}
__device__ __forceinline__ void unpackf2(unsigned long long r, float& x, float& y) {
    asm("mov.b64 {%0, %1}, %2;" : "=f"(x), "=f"(y) : "l"(r));
}

// ---------------------------------------------------------------------------
// HMMA GEMM: C[M,N] = A2[M,KP] . B2[N,KP]^T (+ bias).
// 128x128 CTA tile, BK=32, 256 threads (8 warps, each 32Mx64N).
// 4-stage cp.async ring, ONE __syncthreads per K-iteration.
// ldmatrix + mma.sync m16n8k16 bf16; swizzle seg^(row&3) on 16B segs of 64B rows.
// ---------------------------------------------------------------------------
#define GBM 128
#define GBN 128
#define GBK 32
#define KITERS (KP / GBK)    // 48
#define STAGES 4
#define STAGE_BYTES 16384            // 8KB A + 8KB B
#define SMEM_GEMM (STAGES * STAGE_BYTES)   // 64KB

__global__ __launch_bounds__(256, 2)
void gemm_mma(const __nv_bfloat16* __restrict__ A2,
              const __nv_bfloat16* __restrict__ B2,
              const float* __restrict__ bias,
              float* __restrict__ C, int M, int N) {
    extern __shared__ __align__(128) unsigned char smem[];

    const int tid  = threadIdx.x;
    const int wid  = tid >> 5;
    const int lane = tid & 31;
    const int wm = (wid & 3) * 32;        // warp M offset in tile
    const int wn = (wid >> 2) * 64;       // warp N offset in tile
    const int tm = blockIdx.y * GBM;
    const int tn = blockIdx.x * GBN;

    const uint32_t sbase = smem_to_u32(smem);

    const int lrow = tid >> 1;            // 0..127
    const int lseg = (tid & 1) * 2;       // 0 or 2
    const __nv_bfloat16* gA = A2 + (size_t)(tm + lrow) * KP + lseg * 8;
    const __nv_bfloat16* gB = B2 + (size_t)(tn + lrow) * KP + lseg * 8;
    // in-stage offsets (A at +0, B at +8192)
    const uint32_t oA0 = lrow * 64 + (((lseg + 0) ^ (lrow & 3)) * 16);
    const uint32_t oA1 = lrow * 64 + (((lseg + 1) ^ (lrow & 3)) * 16);
    const uint32_t oB0 = 8192 + lrow * 64 + (((lseg + 0) ^ (lrow & 3)) * 16);
    const uint32_t oB1 = 8192 + lrow * 64 + (((lseg + 1) ^ (lrow & 3)) * 16);

    // Issue loads for iteration `it` into its ring stage; ALWAYS commits a
    // group (empty at the tail) so group counting stays exact.
#define ISSUE_STAGE(it) do {                                                   \
    if ((it) < KITERS) {                                                       \
        int _k0 = (it) * GBK;                                                  \
        uint32_t _bo = sbase + ((it) & (STAGES - 1)) * STAGE_BYTES;            \
        asm volatile("cp.async.cg.shared.global [%0], [%1], 16;"               \
                     :: "r"(_bo + oA0), "l"(gA + _k0));                        \
        asm volatile("cp.async.cg.shared.global [%0], [%1], 16;"               \
                     :: "r"(_bo + oA1), "l"(gA + _k0 + 8));                    \
        asm volatile("cp.async.cg.shared.global [%0], [%1], 16;"               \
                     :: "r"(_bo + oB0), "l"(gB + _k0));                        \
        asm volatile("cp.async.cg.shared.global [%0], [%1], 16;"               \
                     :: "r"(_bo + oB1), "l"(gB + _k0 + 8));                    \
    }                                                                          \
    asm volatile("cp.async.commit_group;");                                    \
} while (0)

    float acc[2][8][4];
#pragma unroll
    for (int i = 0; i < 2; i++)
#pragma unroll
        for (int j = 0; j < 8; j++)
#pragma unroll
            for (int r = 0; r < 4; r++) acc[i][j][r] = 0.0f;

    const int rA0 = wm + (lane & 15);
    const int rA1 = wm + 16 + (lane & 15);
    const int kh  = lane >> 4;

    // prologue: fill STAGES-1 stages
    ISSUE_STAGE(0);
    ISSUE_STAGE(1);
    ISSUE_STAGE(2);

    for (int it = 0; it < KITERS; ++it) {
        // group `it` complete when <= STAGES-2 groups outstanding
        asm volatile("cp.async.wait_group %0;" :: "n"(STAGES - 2));
        __syncthreads();
        // stage (it+3): its buffer was consumed at it-1; barrier above freed it
        ISSUE_STAGE(it + 3);

        const uint32_t aB = sbase + (it & (STAGES - 1)) * STAGE_BYTES;
        const uint32_t bB = aB + 8192;

#pragma unroll
        for (int kk = 0; kk < 2; kk++) {
            const int segl = kk * 2 + kh;
            uint32_t a[2][4];
            {
                uint32_t ad0 = aB + rA0 * 64 + ((segl ^ (rA0 & 3)) * 16);
                asm volatile("ldmatrix.sync.aligned.m8n8.x4.shared.b16 {%0,%1,%2,%3}, [%4];"
                             : "=r"(a[0][0]), "=r"(a[0][1]), "=r"(a[0][2]), "=r"(a[0][3])
                             : "r"(ad0));
                uint32_t ad1 = aB + rA1 * 64 + ((segl ^ (rA1 & 3)) * 16);
                asm volatile("ldmatrix.sync.aligned.m8n8.x4.shared.b16 {%0,%1,%2,%3}, [%4];"
                             : "=r"(a[1][0]), "=r"(a[1][1]), "=r"(a[1][2]), "=r"(a[1][3])
                             : "r"(ad1));
            }
            uint32_t b[4][4];
#pragma unroll
            for (int j2 = 0; j2 < 4; j2++) {
                int rB = wn + j2 * 16 + (lane & 15);
                uint32_t bd = bB + rB * 64 + ((segl ^ (rB & 3)) * 16);
                asm volatile("ldmatrix.sync.aligned.m8n8.x4.shared.b16 {%0,%1,%2,%3}, [%4];"
                             : "=r"(b[j2][0]), "=r"(b[j2][1]), "=r"(b[j2][2]), "=r"(b[j2][3])
                             : "r"(bd));
            }
#pragma unroll
            for (int i = 0; i < 2; i++)
#pragma unroll
                for (int j = 0; j < 8; j++) {
                    uint32_t b0 = b[j >> 1][(j & 1)];
                    uint32_t b1 = b[j >> 1][(j & 1) + 2];
                    asm volatile(
                        "mma.sync.aligned.m16n8k16.row.col.f32.bf16.bf16.f32 "
                        "{%0,%1,%2,%3}, {%4,%5,%6,%7}, {%8,%9}, {%0,%1,%2,%3};"
                        : "+f"(acc[i][j][0]), "+f"(acc[i][j][1]),
                          "+f"(acc[i][j][2]), "+f"(acc[i][j][3])
                        : "r"(a[i][0]), "r"(a[i][1]), "r"(a[i][2]), "r"(a[i][3]),
                          "r"(b0), "r"(b1));
                }
        }
    }

#pragma unroll
    for (int i = 0; i < 2; i++) {
        int row0 = tm + wm + i * 16 + (lane >> 2);
#pragma unroll
        for (int half = 0; half < 2; half++) {
            int row = row0 + half * 8;
            if (row >= M) continue;
#pragma unroll
            for (int j = 0; j < 8; j++) {
                int col = tn + wn + j * 8 + (lane & 3) * 2;
                float2 v;
                v.x = acc[i][j][half * 2 + 0];
                v.y = acc[i][j][half * 2 + 1];
                if (bias) {
                    float2 bb = *(const float2*)(bias + col);
                    v.x += bb.x; v.y += bb.y;
                }
                *(float2*)(C + (size_t)row * N + col) = v;
            }
        }
    }
}

// ---------------------------------------------------------------------------
// conv_x: x fp32 [M,512] -> A2 split-bf16 [M,1536]  (hi | lo | hi)
// ---------------------------------------------------------------------------
__global__ __launch_bounds__(256)
void conv_x_kernel(const float* __restrict__ x, __nv_bfloat16* __restrict__ A2) {
    size_t i = (size_t)blockIdx.x * blockDim.x + threadIdx.x;
    if (i >= (size_t)MROWS * 128) return;
    size_t row = i >> 7;
    int c4 = (int)(i & 127);
    float4 v = *(const float4*)(x + row * 512 + c4 * 4);
    __nv_bfloat16 h0, h1, h2, h3, l0, l1, l2, l3;
    split_bf16(v.x, h0, l0); split_bf16(v.y, h1, l1);
    split_bf16(v.z, h2, l2); split_bf16(v.w, h3, l3);
    uint2 hp = make_uint2(pack2(h0, h1), pack2(h2, h3));
    uint2 lp = make_uint2(pack2(l0, l1), pack2(l2, l3));
    __nv_bfloat16* base = A2 + row * KP + c4 * 4;
    *(uint2*)(base)        = hp;
    *(uint2*)(base + 512)  = lp;
    *(uint2*)(base + 1024) = hp;
}

// ---------------------------------------------------------------------------
// convW: W fp32 [512,N] -> B2 split-bf16 [N,1536] (transposed, hi | hi | lo)
// ---------------------------------------------------------------------------
__global__ __launch_bounds__(1024)
void convW_kernel(const float* __restrict__ W, __nv_bfloat16* __restrict__ B2, int N) {
    __shared__ float t[32][33];
    int n0 = blockIdx.x * 32, k0 = blockIdx.y * 32;
    int tx = threadIdx.x, ty = threadIdx.y;
    t[ty][tx] = W[(size_t)(k0 + ty) * N + n0 + tx];
    __syncthreads();
    int n = n0 + ty, k = k0 + tx;
    float v = t[tx][ty];
    __nv_bfloat16 h, l;
    split_bf16(v, h, l);
    size_t base = (size_t)n * KP + k;
    B2[base]        = h;
    B2[base + 512]  = h;
    B2[base + 1024] = l;
}

// ---------------------------------------------------------------------------
// Local attention: single pass, Cauchy-Schwarz bound as softmax max,
// packed f32x2 FMA for QK dot and PV accumulation.
// ---------------------------------------------------------------------------
__global__ __launch_bounds__(256, 1)
void local_attn_kernel(const float* __restrict__ qkv, __nv_bfloat16* __restrict__ A2) {
    extern __shared__ float sh[];
    float* Ks = sh;                 // [197][64]
    float* Vs = sh + NK_ * DH_;     // [197][64]
    __shared__ int s_maxk2;

    const int blk = blockIdx.x;
    const int b = blk / (H_ * F_);
    const int rem = blk % (H_ * F_);
    const int h = rem / F_;
    const int fi = rem % F_;
    const int t0 = 1 + fi * NP_;
    const int tid = threadIdx.x;

    const size_t bbase = (size_t)b * NTOT * QKVC;
    const int hoff = h * DH_;

    if (tid == 0) s_maxk2 = 0;
    for (int idx = tid; idx < NK_ * (DH_ / 4); idx += blockDim.x) {
        int j = idx >> 4;
        int d4 = idx & 15;
        int tok = (j == 0) ? 0 : (t0 + j - 1);
        const float* kp = qkv + bbase + (size_t)tok * QKVC + DIM_ + hoff + d4 * 4;
        *(float4*)&Ks[j * DH_ + d4 * 4] = *(const float4*)kp;
        *(float4*)&Vs[j * DH_ + d4 * 4] = *(const float4*)(kp + DIM_);
    }
    __syncthreads();

    if (tid < NK_) {
        float kn2 = 0.0f;
#pragma unroll
        for (int i = 0; i < 16; i++) {
            float4 kk = *(const float4*)&Ks[tid * DH_ + i * 4];
            kn2 += kk.x * kk.x + kk.y * kk.y + kk.z * kk.z + kk.w * kk.w;
        }
        atomicMax(&s_maxk2, __float_as_int(kn2));
    }
    __syncthreads();
    const float maxk2 = __int_as_float(s_maxk2);

    const int qi = tid;
    if (qi >= NP_) return;
    const int qtok = t0 + qi;
    const float scale = 0.125f;

    const float* qp = qkv + bbase + (size_t)qtok * QKVC + hoff;
    unsigned long long q2[32];
    float qn2 = 0.0f;
#pragma unroll
    for (int i = 0; i < 16; i++) {
        float4 t = *(const float4*)&qp[i * 4];
        float x0 = t.x * scale, x1 = t.y * scale, x2 = t.z * scale, x3 = t.w * scale;
        qn2 += x0 * x0 + x1 * x1 + x2 * x2 + x3 * x3;
        q2[2 * i]     = packf2(x0, x1);
        q2[2 * i + 1] = packf2(x2, x3);
    }
    const float m = sqrtf(qn2 * maxk2) + 1e-6f;

    unsigned long long acc2[32];
#pragma unroll
    for (int i = 0; i < 32; i++) acc2[i] = 0ULL;
    float l = 0.0f;

    for (int j = 0; j < NK_; j++) {
        const unsigned long long* kr = (const unsigned long long*)&Ks[j * DH_];
        unsigned long long s2a = 0ULL, s2b = 0ULL, s2c = 0ULL, s2d = 0ULL;
#pragma unroll
        for (int i = 0; i < 8; i++) {
            s2a = ffma2(q2[4 * i + 0], kr[4 * i + 0], s2a);
            s2b = ffma2(q2[4 * i + 1], kr[4 * i + 1], s2b);
            s2c = ffma2(q2[4 * i + 2], kr[4 * i + 2], s2c);
            s2d = ffma2(q2[4 * i + 3], kr[4 * i + 3], s2d);
        }
        float a0, a1, b0, b1, c0, c1, d0, d1;
        unpackf2(s2a, a0, a1); unpackf2(s2b, b0, b1);
        unpackf2(s2c, c0, c1); unpackf2(s2d, d0, d1);
        float s = ((a0 + a1) + (b0 + b1)) + ((c0 + c1) + (d0 + d1));
        float p = __expf(s - m);
        l += p;
        unsigned long long p2 = packf2(p, p);
        const unsigned long long* vr = (const unsigned long long*)&Vs[j * DH_];
#pragma unroll
        for (int i = 0; i < 32; i++) acc2[i] = ffma2(p2, vr[i], acc2[i]);
    }

    const float inv = 1.0f / l;
    __nv_bfloat16* base = A2 + ((size_t)b * NTOT + qtok) * KP + hoff;
#pragma unroll
    for (int i = 0; i < 16; i++) {
        float v0, v1, v2, v3;
        unpackf2(acc2[2 * i], v0, v1);
        unpackf2(acc2[2 * i + 1], v2, v3);
        v0 *= inv; v1 *= inv; v2 *= inv; v3 *= inv;
        __nv_bfloat16 h0, h1, h2, h3, l0, l1, l2, l3;
        split_bf16(v0, h0, l0); split_bf16(v1, h1, l1);
        split_bf16(v2, h2, l2); split_bf16(v3, h3, l3);
        uint2 hp = make_uint2(pack2(h0, h1), pack2(h2, h3));
        uint2 lp = make_uint2(pack2(l0, l1), pack2(l2, l3));
        *(uint2*)(base + i * 4)        = hp;
        *(uint2*)(base + 512 + i * 4)  = lp;
        *(uint2*)(base + 1024 + i * 4) = hp;
    }
}

// ---------------------------------------------------------------------------
// CLS attention: one block per (b,h). Writes split-bf16 directly.
// ---------------------------------------------------------------------------
__global__ __launch_bounds__(256)
void cls_attn_kernel(const float* __restrict__ qkv, __nv_bfloat16* __restrict__ A2) {
    __shared__ float qs[DH_];
    __shared__ float sc[NTOT];
    __shared__ float redbuf[8];
    __shared__ float accs[4][DH_];

    const int b = blockIdx.x / H_;
    const int h = blockIdx.x % H_;
    const int tid = threadIdx.x;
    const int lane = tid & 31;
    const int warp = tid >> 5;
    const size_t bbase = (size_t)b * NTOT * QKVC;
    const int hoff = h * DH_;

    if (tid < DH_) qs[tid] = qkv[bbase + hoff + tid] * 0.125f;
    __syncthreads();

    float lmax = -1e30f;
    for (int j = tid; j < NTOT; j += 256) {
        const float* kp = qkv + bbase + (size_t)j * QKVC + DIM_ + hoff;
        float s = 0.0f;
#pragma unroll
        for (int i = 0; i < 16; i++) {
            float4 kk = *(const float4*)&kp[i * 4];
            float4 qq = *(const float4*)&qs[i * 4];
            s += qq.x * kk.x + qq.y * kk.y + qq.z * kk.z + qq.w * kk.w;
        }
        sc[j] = s;
        lmax = fmaxf(lmax, s);
    }
#pragma unroll
    for (int o = 16; o; o >>= 1) lmax = fmaxf(lmax, __shfl_xor_sync(~0u, lmax, o));
    if (lane == 0) redbuf[warp] = lmax;
    __syncthreads();
    float m = fmaxf(fmaxf(fmaxf(redbuf[0], redbuf[1]), fmaxf(redbuf[2], redbuf[3])),
                    fmaxf(fmaxf(redbuf[4], redbuf[5]), fmaxf(redbuf[6], redbuf[7])));
    __syncthreads();

    float lsum = 0.0f;
    for (int j = tid; j < NTOT; j += 256) {
        float p = __expf(sc[j] - m);
        sc[j] = p;
        lsum += p;
    }
#pragma unroll
    for (int o = 16; o; o >>= 1) lsum += __shfl_xor_sync(~0u, lsum, o);
    if (lane == 0) redbuf[warp] = lsum;
    __syncthreads();
    float l = redbuf[0] + redbuf[1] + redbuf[2] + redbuf[3] +
              redbuf[4] + redbuf[5] + redbuf[6] + redbuf[7];

    const int d = tid & 63;
    const int g = tid >> 6;
    float acc = 0.0f;
    for (int j = g; j < NTOT; j += 4)
        acc += sc[j] * qkv[bbase + (size_t)j * QKVC + 2 * DIM_ + hoff + d];
    accs[g][d] = acc;
    __syncthreads();
    if (tid < DH_) {
        float o = (accs[0][tid] + accs[1][tid] + accs[2][tid] + accs[3][tid]) / l;
        __nv_bfloat16 hh, ll;
        split_bf16(o, hh, ll);
        __nv_bfloat16* base = A2 + (size_t)b * NTOT * KP + hoff + tid;
        base[0]    = hh;
        base[512]  = ll;
        base[1024] = hh;
    }
}

// ---------------------------------------------------------------------------
extern "C" void kernel_launch(void* const* d_in, const int* in_sizes, int n_in,
                              void* d_out, int out_size) {
    const float* x    = (const float*)d_in[0];
    const float* Wqkv = (const float*)d_in[1];
    const float* Wout = (const float*)d_in[2];
    const float* bout = (const float*)d_in[3];
    float* out = (float*)d_out;

    float* qkv = nullptr;
    __nv_bfloat16 *A2x = nullptr, *A2att = nullptr, *B2qkv = nullptr, *B2out = nullptr;
    cudaGetSymbolAddress((void**)&qkv, g_qkv);
    cudaGetSymbolAddress((void**)&A2x, g_A2x);
    cudaGetSymbolAddress((void**)&A2att, g_A2att);
    cudaGetSymbolAddress((void**)&B2qkv, g_B2qkv);
    cudaGetSymbolAddress((void**)&B2out, g_B2out);

    cudaFuncSetAttribute(gemm_mma,
                         cudaFuncAttributeMaxDynamicSharedMemorySize, SMEM_GEMM);

    // conversions
    {
        size_t tot = (size_t)MROWS * 128;
        conv_x_kernel<<<(unsigned)((tot + 255) / 256), 256>>>(x, A2x);
        convW_kernel<<<dim3(QKVC / 32, DIM_ / 32), dim3(32, 32)>>>(Wqkv, B2qkv, QKVC);
        convW_kernel<<<dim3(DIM_ / 32, DIM_ / 32), dim3(32, 32)>>>(Wout, B2out, DIM_);
    }

    // 1) qkv = x @ W_qkv  (HMMA split-bf16) -> fp32
    gemm_mma<<<dim3(QKVC / GBN, MPAD / GBM), 256, SMEM_GEMM>>>(
        A2x, B2qkv, nullptr, qkv, MROWS, QKVC);

    // 2) local attention (512 blocks)
    {
        int smem = 2 * NK_ * DH_ * (int)sizeof(float);
        cudaFuncSetAttribute(local_attn_kernel,
                             cudaFuncAttributeMaxDynamicSharedMemorySize, smem);
        local_attn_kernel<<<B_ * H_ * F_, 256, smem>>>(qkv, A2att);
    }

    // 3) cls attention
    cls_attn_kernel<<<B_ * H_, 256>>>(qkv, A2att);

    // 4) out = att @ W_out + b_out
    gemm_mma<<<dim3(DIM_ / GBN, MPAD / GBM), 256, SMEM_GEMM>>>(
        A2att, B2out, bout, out, MROWS, DIM_);
}

// round 11
// speedup vs baseline: 1.8685x; 1.0057x over previous
#include <cuda_runtime.h>
#include <cuda_bf16.h>
#include <cstdint>

// Problem constants
#define B_   4
#define F_   16
#define NP_  196
#define DIM_ 512
#define H_   8
#define DH_  64
#define NTOT 3137            // 1 + F*NP
#define MROWS (B_ * NTOT)    // 12548
#define MPAD  12800          // 50 * 256
#define QKVC (3 * H_ * DH_)  // 1536
#define NK_  197             // cls + 196 local keys
#define KP   1536            // split-bf16 K' = 3*512

// ---------------------------------------------------------------------------
// Scratch (allocation-free: __device__ globals)
// ---------------------------------------------------------------------------
__device__ float         g_qkv[(size_t)MROWS * QKVC];        // fp32 qkv (~77MB)
__device__ __nv_bfloat16 g_A2x[(size_t)MPAD * KP];           // x split-bf16
__device__ __nv_bfloat16 g_A2att[(size_t)MPAD * KP];         // attn out split-bf16
__device__ __nv_bfloat16 g_B2qkv[(size_t)QKVC * KP];         // W_qkv^T split-bf16
__device__ __nv_bfloat16 g_B2out[(size_t)DIM_ * KP];         // W_out^T split-bf16

// ---------------------------------------------------------------------------
__device__ __forceinline__ uint32_t smem_to_u32(const void* p) {
    uint32_t a;
    asm("{ .reg .u64 t; cvta.to.shared.u64 t, %1; cvt.u32.u64 %0, t; }"
        : "=r"(a) : "l"(p));
    return a;
}

// split helpers
__device__ __forceinline__ void split_bf16(float v, __nv_bfloat16& h, __nv_bfloat16& l) {
    h = __float2bfloat16_rn(v);
    l = __float2bfloat16_rn(v - __bfloat162float(h));
}
__device__ __forceinline__ uint32_t pack2(__nv_bfloat16 a, __nv_bfloat16 b) {
    __nv_bfloat162 t = __halves2bfloat162(a, b);
    return *(uint32_t*)&t;
}

// packed f32x2 helpers (sm_100+)
__device__ __forceinline__ unsigned long long ffma2(unsigned long long a,
                                                    unsigned long long b,
                                                    unsigned long long c) {
    unsigned long long d;
    asm("fma.rn.f32x2 %0, %1, %2, %3;" : "=l"(d) : "l"(a), "l"(b), "l"(c));
    return d;
}
__device__ __forceinline__ unsigned long long packf2(float x, float y) {
    unsigned long long r;
    asm("mov.b64 %0, {%1, %2};" : "=l"(r) : "f"(x), "f"(y));
    return r;
}
__device__ __forceinline__ void unpackf2(unsigned long long r, float& x, float& y) {
    asm("mov.b64 {%0, %1}, %2;" : "=f"(x), "=f"(y) : "l"(r));
}

// ---------------------------------------------------------------------------
// HMMA GEMM: C[M,N] = A2[M,KP] . B2[N,KP]^T (+ bias).
// CTA tile 256x128, BK=32, 256 threads = 8 warps in 4(m) x 2(n) grid,
// warp tile 64x64 (128 accum regs). 4-stage cp.async ring, one barrier/iter.
// ldmatrix + mma.sync m16n8k16 bf16; swizzle seg^(row&3) on 16B segs, 64B rows.
// ---------------------------------------------------------------------------
#define GBM 256
#define GBN 128
#define GBK 32
#define KITERS (KP / GBK)          // 48
#define STAGES 4
#define A_BYTES (GBM * GBK * 2)    // 16384
#define B_BYTES (GBN * GBK * 2)    // 8192
#define STAGE_BYTES (A_BYTES + B_BYTES)      // 24576
#define SMEM_GEMM (STAGES * STAGE_BYTES)     // 98304

__global__ __launch_bounds__(256, 1)
void gemm_mma(const __nv_bfloat16* __restrict__ A2,
              const __nv_bfloat16* __restrict__ B2,
              const float* __restrict__ bias,
              float* __restrict__ C, int M, int N) {
    extern __shared__ __align__(128) unsigned char smem[];

    const int tid  = threadIdx.x;
    const int wid  = tid >> 5;
    const int lane = tid & 31;
    const int wm = (wid & 3) * 64;        // warp M offset (4 groups)
    const int wn = (wid >> 2) * 64;       // warp N offset (2 groups)
    const int tm = blockIdx.y * GBM;
    const int tn = blockIdx.x * GBN;

    const uint32_t sbase = smem_to_u32(smem);

    // global->smem copy plan: A needs 1024 16B-chunks (4/thread),
    // B needs 512 (2/thread). chunk c -> row=c>>2, seg=c&3.
    const __nv_bfloat16* gAp[4];
    uint32_t oA[4];
#pragma unroll
    for (int t = 0; t < 4; t++) {
        int c = tid + t * 256;
        int row = c >> 2, seg = c & 3;
        gAp[t] = A2 + (size_t)(tm + row) * KP + seg * 8;
        oA[t] = row * 64 + ((seg ^ (row & 3)) * 16);
    }
    const __nv_bfloat16* gBp[2];
    uint32_t oB[2];
#pragma unroll
    for (int t = 0; t < 2; t++) {
        int c = tid + t * 256;
        int row = c >> 2, seg = c & 3;
        gBp[t] = B2 + (size_t)(tn + row) * KP + seg * 8;
        oB[t] = A_BYTES + row * 64 + ((seg ^ (row & 3)) * 16);
    }

#define ISSUE_STAGE(it) do {                                                   \
    if ((it) < KITERS) {                                                       \
        int _k0 = (it) * GBK;                                                  \
        uint32_t _bo = sbase + ((it) & (STAGES - 1)) * STAGE_BYTES;            \
        asm volatile("cp.async.cg.shared.global [%0], [%1], 16;"               \
                     :: "r"(_bo + oA[0]), "l"(gAp[0] + _k0));                  \
        asm volatile("cp.async.cg.shared.global [%0], [%1], 16;"               \
                     :: "r"(_bo + oA[1]), "l"(gAp[1] + _k0));                  \
        asm volatile("cp.async.cg.shared.global [%0], [%1], 16;"               \
                     :: "r"(_bo + oA[2]), "l"(gAp[2] + _k0));                  \
        asm volatile("cp.async.cg.shared.global [%0], [%1], 16;"               \
                     :: "r"(_bo + oA[3]), "l"(gAp[3] + _k0));                  \
        asm volatile("cp.async.cg.shared.global [%0], [%1], 16;"               \
                     :: "r"(_bo + oB[0]), "l"(gBp[0] + _k0));                  \
        asm volatile("cp.async.cg.shared.global [%0], [%1], 16;"               \
                     :: "r"(_bo + oB[1]), "l"(gBp[1] + _k0));                  \
    }                                                                          \
    asm volatile("cp.async.commit_group;");                                    \
} while (0)

    float acc[4][8][4];
#pragma unroll
    for (int i = 0; i < 4; i++)
#pragma unroll
        for (int j = 0; j < 8; j++)
#pragma unroll
            for (int r = 0; r < 4; r++) acc[i][j][r] = 0.0f;

    const int rbase = lane & 15;          // ldmatrix row-in-subtile
    const int kh = lane >> 4;             // k-half selector

    ISSUE_STAGE(0);
    ISSUE_STAGE(1);
    ISSUE_STAGE(2);

    for (int it = 0; it < KITERS; ++it) {
        asm volatile("cp.async.wait_group %0;" :: "n"(STAGES - 2));
        __syncthreads();
        ISSUE_STAGE(it + 3);

        const uint32_t aB = sbase + (it & (STAGES - 1)) * STAGE_BYTES;
        const uint32_t bB = aB + A_BYTES;

#pragma unroll
        for (int kk = 0; kk < 2; kk++) {
            const int segl = kk * 2 + kh;
            uint32_t a[4][4];
#pragma unroll
            for (int i = 0; i < 4; i++) {
                int rA = wm + i * 16 + rbase;
                uint32_t ad = aB + rA * 64 + ((segl ^ (rA & 3)) * 16);
                asm volatile("ldmatrix.sync.aligned.m8n8.x4.shared.b16 {%0,%1,%2,%3}, [%4];"
                             : "=r"(a[i][0]), "=r"(a[i][1]), "=r"(a[i][2]), "=r"(a[i][3])
                             : "r"(ad));
            }
            uint32_t b[4][4];
#pragma unroll
            for (int j2 = 0; j2 < 4; j2++) {
                int rB = wn + j2 * 16 + rbase;
                uint32_t bd = bB + rB * 64 + ((segl ^ (rB & 3)) * 16);
                asm volatile("ldmatrix.sync.aligned.m8n8.x4.shared.b16 {%0,%1,%2,%3}, [%4];"
                             : "=r"(b[j2][0]), "=r"(b[j2][1]), "=r"(b[j2][2]), "=r"(b[j2][3])
                             : "r"(bd));
            }
#pragma unroll
            for (int i = 0; i < 4; i++)
#pragma unroll
                for (int j = 0; j < 8; j++) {
                    uint32_t b0 = b[j >> 1][(j & 1)];
                    uint32_t b1 = b[j >> 1][(j & 1) + 2];
                    asm volatile(
                        "mma.sync.aligned.m16n8k16.row.col.f32.bf16.bf16.f32 "
                        "{%0,%1,%2,%3}, {%4,%5,%6,%7}, {%8,%9}, {%0,%1,%2,%3};"
                        : "+f"(acc[i][j][0]), "+f"(acc[i][j][1]),
                          "+f"(acc[i][j][2]), "+f"(acc[i][j][3])
                        : "r"(a[i][0]), "r"(a[i][1]), "r"(a[i][2]), "r"(a[i][3]),
                          "r"(b0), "r"(b1));
                }
        }
    }

#pragma unroll
    for (int i = 0; i < 4; i++) {
        int row0 = tm + wm + i * 16 + (lane >> 2);
#pragma unroll
        for (int half = 0; half < 2; half++) {
            int row = row0 + half * 8;
            if (row >= M) continue;
#pragma unroll
            for (int j = 0; j < 8; j++) {
                int col = tn + wn + j * 8 + (lane & 3) * 2;
                float2 v;
                v.x = acc[i][j][half * 2 + 0];
                v.y = acc[i][j][half * 2 + 1];
                if (bias) {
                    float2 bb = *(const float2*)(bias + col);
                    v.x += bb.x; v.y += bb.y;
                }
                *(float2*)(C + (size_t)row * N + col) = v;
            }
        }
    }
}

// ---------------------------------------------------------------------------
// conv_x: x fp32 [M,512] -> A2 split-bf16 [M,1536]  (hi | lo | hi)
// ---------------------------------------------------------------------------
__global__ __launch_bounds__(256)
void conv_x_kernel(const float* __restrict__ x, __nv_bfloat16* __restrict__ A2) {
    size_t i = (size_t)blockIdx.x * blockDim.x + threadIdx.x;
    if (i >= (size_t)MROWS * 128) return;
    size_t row = i >> 7;
    int c4 = (int)(i & 127);
    float4 v = *(const float4*)(x + row * 512 + c4 * 4);
    __nv_bfloat16 h0, h1, h2, h3, l0, l1, l2, l3;
    split_bf16(v.x, h0, l0); split_bf16(v.y, h1, l1);
    split_bf16(v.z, h2, l2); split_bf16(v.w, h3, l3);
    uint2 hp = make_uint2(pack2(h0, h1), pack2(h2, h3));
    uint2 lp = make_uint2(pack2(l0, l1), pack2(l2, l3));
    __nv_bfloat16* base = A2 + row * KP + c4 * 4;
    *(uint2*)(base)        = hp;
    *(uint2*)(base + 512)  = lp;
    *(uint2*)(base + 1024) = hp;
}

// ---------------------------------------------------------------------------
// convW: W fp32 [512,N] -> B2 split-bf16 [N,1536] (transposed, hi | hi | lo)
// ---------------------------------------------------------------------------
__global__ __launch_bounds__(1024)
void convW_kernel(const float* __restrict__ W, __nv_bfloat16* __restrict__ B2, int N) {
    __shared__ float t[32][33];
    int n0 = blockIdx.x * 32, k0 = blockIdx.y * 32;
    int tx = threadIdx.x, ty = threadIdx.y;
    t[ty][tx] = W[(size_t)(k0 + ty) * N + n0 + tx];
    __syncthreads();
    int n = n0 + ty, k = k0 + tx;
    float v = t[tx][ty];
    __nv_bfloat16 h, l;
    split_bf16(v, h, l);
    size_t base = (size_t)n * KP + k;
    B2[base]        = h;
    B2[base + 512]  = h;
    B2[base + 1024] = l;
}

// ---------------------------------------------------------------------------
// Local attention: single pass, Cauchy-Schwarz bound as softmax max,
// packed f32x2 FMA for QK dot and PV accumulation.
// ---------------------------------------------------------------------------
__global__ __launch_bounds__(256, 1)
void local_attn_kernel(const float* __restrict__ qkv, __nv_bfloat16* __restrict__ A2) {
    extern __shared__ float sh[];
    float* Ks = sh;                 // [197][64]
    float* Vs = sh + NK_ * DH_;     // [197][64]
    __shared__ int s_maxk2;

    const int blk = blockIdx.x;
    const int b = blk / (H_ * F_);
    const int rem = blk % (H_ * F_);
    const int h = rem / F_;
    const int fi = rem % F_;
    const int t0 = 1 + fi * NP_;
    const int tid = threadIdx.x;

    const size_t bbase = (size_t)b * NTOT * QKVC;
    const int hoff = h * DH_;

    if (tid == 0) s_maxk2 = 0;
    for (int idx = tid; idx < NK_ * (DH_ / 4); idx += blockDim.x) {
        int j = idx >> 4;
        int d4 = idx & 15;
        int tok = (j == 0) ? 0 : (t0 + j - 1);
        const float* kp = qkv + bbase + (size_t)tok * QKVC + DIM_ + hoff + d4 * 4;
        *(float4*)&Ks[j * DH_ + d4 * 4] = *(const float4*)kp;
        *(float4*)&Vs[j * DH_ + d4 * 4] = *(const float4*)(kp + DIM_);
    }
    __syncthreads();

    if (tid < NK_) {
        float kn2 = 0.0f;
#pragma unroll
        for (int i = 0; i < 16; i++) {
            float4 kk = *(const float4*)&Ks[tid * DH_ + i * 4];
            kn2 += kk.x * kk.x + kk.y * kk.y + kk.z * kk.z + kk.w * kk.w;
        }
        atomicMax(&s_maxk2, __float_as_int(kn2));
    }
    __syncthreads();
    const float maxk2 = __int_as_float(s_maxk2);

    const int qi = tid;
    if (qi >= NP_) return;
    const int qtok = t0 + qi;
    const float scale = 0.125f;

    const float* qp = qkv + bbase + (size_t)qtok * QKVC + hoff;
    unsigned long long q2[32];
    float qn2 = 0.0f;
#pragma unroll
    for (int i = 0; i < 16; i++) {
        float4 t = *(const float4*)&qp[i * 4];
        float x0 = t.x * scale, x1 = t.y * scale, x2 = t.z * scale, x3 = t.w * scale;
        qn2 += x0 * x0 + x1 * x1 + x2 * x2 + x3 * x3;
        q2[2 * i]     = packf2(x0, x1);
        q2[2 * i + 1] = packf2(x2, x3);
    }
    const float m = sqrtf(qn2 * maxk2) + 1e-6f;

    unsigned long long acc2[32];
#pragma unroll
    for (int i = 0; i < 32; i++) acc2[i] = 0ULL;
    float l = 0.0f;

    for (int j = 0; j < NK_; j++) {
        const unsigned long long* kr = (const unsigned long long*)&Ks[j * DH_];
        unsigned long long s2a = 0ULL, s2b = 0ULL, s2c = 0ULL, s2d = 0ULL;
#pragma unroll
        for (int i = 0; i < 8; i++) {
            s2a = ffma2(q2[4 * i + 0], kr[4 * i + 0], s2a);
            s2b = ffma2(q2[4 * i + 1], kr[4 * i + 1], s2b);
            s2c = ffma2(q2[4 * i + 2], kr[4 * i + 2], s2c);
            s2d = ffma2(q2[4 * i + 3], kr[4 * i + 3], s2d);
        }
        float a0, a1, b0, b1, c0, c1, d0, d1;
        unpackf2(s2a, a0, a1); unpackf2(s2b, b0, b1);
        unpackf2(s2c, c0, c1); unpackf2(s2d, d0, d1);
        float s = ((a0 + a1) + (b0 + b1)) + ((c0 + c1) + (d0 + d1));
        float p = __expf(s - m);
        l += p;
        unsigned long long p2 = packf2(p, p);
        const unsigned long long* vr = (const unsigned long long*)&Vs[j * DH_];
#pragma unroll
        for (int i = 0; i < 32; i++) acc2[i] = ffma2(p2, vr[i], acc2[i]);
    }

    const float inv = 1.0f / l;
    __nv_bfloat16* base = A2 + ((size_t)b * NTOT + qtok) * KP + hoff;
#pragma unroll
    for (int i = 0; i < 16; i++) {
        float v0, v1, v2, v3;
        unpackf2(acc2[2 * i], v0, v1);
        unpackf2(acc2[2 * i + 1], v2, v3);
        v0 *= inv; v1 *= inv; v2 *= inv; v3 *= inv;
        __nv_bfloat16 h0, h1, h2, h3, l0, l1, l2, l3;
        split_bf16(v0, h0, l0); split_bf16(v1, h1, l1);
        split_bf16(v2, h2, l2); split_bf16(v3, h3, l3);
        uint2 hp = make_uint2(pack2(h0, h1), pack2(h2, h3));
        uint2 lp = make_uint2(pack2(l0, l1), pack2(l2, l3));
        *(uint2*)(base + i * 4)        = hp;
        *(uint2*)(base + 512 + i * 4)  = lp;
        *(uint2*)(base + 1024 + i * 4) = hp;
    }
}

// ---------------------------------------------------------------------------
// CLS attention: one block per (b,h). Writes split-bf16 directly.
// ---------------------------------------------------------------------------
__global__ __launch_bounds__(256)
void cls_attn_kernel(const float* __restrict__ qkv, __nv_bfloat16* __restrict__ A2) {
    __shared__ float qs[DH_];
    __shared__ float sc[NTOT];
    __shared__ float redbuf[8];
    __shared__ float accs[4][DH_];

    const int b = blockIdx.x / H_;
    const int h = blockIdx.x % H_;
    const int tid = threadIdx.x;
    const int lane = tid & 31;
    const int warp = tid >> 5;
    const size_t bbase = (size_t)b * NTOT * QKVC;
    const int hoff = h * DH_;

    if (tid < DH_) qs[tid] = qkv[bbase + hoff + tid] * 0.125f;
    __syncthreads();

    float lmax = -1e30f;
    for (int j = tid; j < NTOT; j += 256) {
        const float* kp = qkv + bbase + (size_t)j * QKVC + DIM_ + hoff;
        float s = 0.0f;
#pragma unroll
        for (int i = 0; i < 16; i++) {
            float4 kk = *(const float4*)&kp[i * 4];
            float4 qq = *(const float4*)&qs[i * 4];
            s += qq.x * kk.x + qq.y * kk.y + qq.z * kk.z + qq.w * kk.w;
        }
        sc[j] = s;
        lmax = fmaxf(lmax, s);
    }
#pragma unroll
    for (int o = 16; o; o >>= 1) lmax = fmaxf(lmax, __shfl_xor_sync(~0u, lmax, o));
    if (lane == 0) redbuf[warp] = lmax;
    __syncthreads();
    float m = fmaxf(fmaxf(fmaxf(redbuf[0], redbuf[1]), fmaxf(redbuf[2], redbuf[3])),
                    fmaxf(fmaxf(redbuf[4], redbuf[5]), fmaxf(redbuf[6], redbuf[7])));
    __syncthreads();

    float lsum = 0.0f;
    for (int j = tid; j < NTOT; j += 256) {
        float p = __expf(sc[j] - m);
        sc[j] = p;
        lsum += p;
    }
#pragma unroll
    for (int o = 16; o; o >>= 1) lsum += __shfl_xor_sync(~0u, lsum, o);
    if (lane == 0) redbuf[warp] = lsum;
    __syncthreads();
    float l = redbuf[0] + redbuf[1] + redbuf[2] + redbuf[3] +
              redbuf[4] + redbuf[5] + redbuf[6] + redbuf[7];

    const int d = tid & 63;
    const int g = tid >> 6;
    float acc = 0.0f;
    for (int j = g; j < NTOT; j += 4)
        acc += sc[j] * qkv[bbase + (size_t)j * QKVC + 2 * DIM_ + hoff + d];
    accs[g][d] = acc;
    __syncthreads();
    if (tid < DH_) {
        float o = (accs[0][tid] + accs[1][tid] + accs[2][tid] + accs[3][tid]) / l;
        __nv_bfloat16 hh, ll;
        split_bf16(o, hh, ll);
        __nv_bfloat16* base = A2 + (size_t)b * NTOT * KP + hoff + tid;
        base[0]    = hh;
        base[512]  = ll;
        base[1024] = hh;
    }
}

// ---------------------------------------------------------------------------
extern "C" void kernel_launch(void* const* d_in, const int* in_sizes, int n_in,
                              void* d_out, int out_size) {
    const float* x    = (const float*)d_in[0];
    const float* Wqkv = (const float*)d_in[1];
    const float* Wout = (const float*)d_in[2];
    const float* bout = (const float*)d_in[3];
    float* out = (float*)d_out;

    float* qkv = nullptr;
    __nv_bfloat16 *A2x = nullptr, *A2att = nullptr, *B2qkv = nullptr, *B2out = nullptr;
    cudaGetSymbolAddress((void**)&qkv, g_qkv);
    cudaGetSymbolAddress((void**)&A2x, g_A2x);
    cudaGetSymbolAddress((void**)&A2att, g_A2att);
    cudaGetSymbolAddress((void**)&B2qkv, g_B2qkv);
    cudaGetSymbolAddress((void**)&B2out, g_B2out);

    cudaFuncSetAttribute(gemm_mma,
                         cudaFuncAttributeMaxDynamicSharedMemorySize, SMEM_GEMM);

    // conversions
    {
        size_t tot = (size_t)MROWS * 128;
        conv_x_kernel<<<(unsigned)((tot + 255) / 256), 256>>>(x, A2x);
        convW_kernel<<<dim3(QKVC / 32, DIM_ / 32), dim3(32, 32)>>>(Wqkv, B2qkv, QKVC);
        convW_kernel<<<dim3(DIM_ / 32, DIM_ / 32), dim3(32, 32)>>>(Wout, B2out, DIM_);
    }

    // 1) qkv = x @ W_qkv  (HMMA split-bf16) -> fp32
    gemm_mma<<<dim3(QKVC / GBN, MPAD / GBM), 256, SMEM_GEMM>>>(
        A2x, B2qkv, nullptr, qkv, MROWS, QKVC);

    // 2) local attention (512 blocks)
    {
        int smem = 2 * NK_ * DH_ * (int)sizeof(float);
        cudaFuncSetAttribute(local_attn_kernel,
                             cudaFuncAttributeMaxDynamicSharedMemorySize, smem);
        local_attn_kernel<<<B_ * H_ * F_, 256, smem>>>(qkv, A2att);
    }

    // 3) cls attention
    cls_attn_kernel<<<B_ * H_, 256>>>(qkv, A2att);

    // 4) out = att @ W_out + b_out
    gemm_mma<<<dim3(DIM_ / GBN, MPAD / GBM), 256, SMEM_GEMM>>>(
        A2att, B2out, bout, out, MROWS, DIM_);
}

// round 12
// speedup vs baseline: 2.1591x; 1.1555x over previous
#include <cuda_runtime.h>
#include <cuda_bf16.h>
#include <cstdint>

// Problem constants
#define B_   4
#define F_   16
#define NP_  196
#define DIM_ 512
#define H_   8
#define DH_  64
#define NTOT 3137            // 1 + F*NP
#define MROWS (B_ * NTOT)    // 12548
#define MPAD  12800          // 50 * 256 (also covers 99*128=12672)
#define QKVC (3 * H_ * DH_)  // 1536
#define NK_  197             // cls + 196 local keys
#define KP   1536            // split-bf16 K' = 3*512

// ---------------------------------------------------------------------------
// Scratch (allocation-free: __device__ globals)
// ---------------------------------------------------------------------------
__device__ float         g_qkv[(size_t)MROWS * QKVC];        // fp32 qkv (~77MB)
__device__ __nv_bfloat16 g_A2x[(size_t)MPAD * KP];           // x split-bf16
__device__ __nv_bfloat16 g_A2att[(size_t)MPAD * KP];         // attn out split-bf16
__device__ __nv_bfloat16 g_B2qkv[(size_t)QKVC * KP];         // W_qkv^T split-bf16
__device__ __nv_bfloat16 g_B2out[(size_t)DIM_ * KP];         // W_out^T split-bf16

// ---------------------------------------------------------------------------
__device__ __forceinline__ uint32_t smem_to_u32(const void* p) {
    uint32_t a;
    asm("{ .reg .u64 t; cvta.to.shared.u64 t, %1; cvt.u32.u64 %0, t; }"
        : "=r"(a) : "l"(p));
    return a;
}

__device__ __forceinline__ void split_bf16(float v, __nv_bfloat16& h, __nv_bfloat16& l) {
    h = __float2bfloat16_rn(v);
    l = __float2bfloat16_rn(v - __bfloat162float(h));
}
__device__ __forceinline__ uint32_t pack2(__nv_bfloat16 a, __nv_bfloat16 b) {
    __nv_bfloat162 t = __halves2bfloat162(a, b);
    return *(uint32_t*)&t;
}

// packed f32x2 helpers (sm_100+)
__device__ __forceinline__ unsigned long long ffma2(unsigned long long a,
                                                    unsigned long long b,
                                                    unsigned long long c) {
    unsigned long long d;
    asm("fma.rn.f32x2 %0, %1, %2, %3;" : "=l"(d) : "l"(a), "l"(b), "l"(c));
    return d;
}
__device__ __forceinline__ unsigned long long packf2(float x, float y) {
    unsigned long long r;
    asm("mov.b64 %0, {%1, %2};" : "=l"(r) : "f"(x), "f"(y));
    return r;
}
__device__ __forceinline__ void unpackf2(unsigned long long r, float& x, float& y) {
    asm("mov.b64 {%0, %1}, %2;" : "=f"(x), "=f"(y) : "l"(r));
}

#define LDSM4(r, addr) \
    asm volatile("ldmatrix.sync.aligned.m8n8.x4.shared.b16 {%0,%1,%2,%3}, [%4];" \
                 : "=r"((r)[0]), "=r"((r)[1]), "=r"((r)[2]), "=r"((r)[3]) \
                 : "r"(addr))
#define CPA16(dst, src) \
    asm volatile("cp.async.cg.shared.global [%0], [%1], 16;" :: "r"(dst), "l"(src))

// ---------------------------------------------------------------------------
// HMMA GEMM (templated on MS = m16-subtiles per warp: 4 -> 256x128 CTA tile,
// 2 -> 128x128). BK=32, 256 threads, 8 warps 4(m)x2(n), warp tile (MS*16)x64.
// 4-stage cp.async ring, one barrier/iter. All LDSMs of an iteration are
// hoisted ahead of all MMAs so load latency hides under the MMA stream.
// ---------------------------------------------------------------------------
#define GBK 32
#define KITERS (KP / GBK)          // 48
#define STAGES 4

template <int MS>
__global__ __launch_bounds__(256, 1)
void gemm_mma(const __nv_bfloat16* __restrict__ A2,
              const __nv_bfloat16* __restrict__ B2,
              const float* __restrict__ bias,
              float* __restrict__ C, int M, int N) {
    constexpr int GBMt = MS * 64;
    constexpr int A_B  = GBMt * 64;          // bytes of A per stage
    constexpr int STG  = A_B + 8192;         // stage bytes (B = 128*64)
    extern __shared__ __align__(128) unsigned char smem[];

    const int tid  = threadIdx.x;
    const int wid  = tid >> 5;
    const int lane = tid & 31;
    const int wm = (wid & 3) * (MS * 16);
    const int wn = (wid >> 2) * 64;
    const int tm = blockIdx.y * GBMt;
    const int tn = blockIdx.x * 128;

    const uint32_t sbase = smem_to_u32(smem);

    // copy plan: A = GBMt*4 16B chunks (MS per thread), B = 512 chunks (2/thread)
    const __nv_bfloat16* gAp[MS];
    uint32_t oA[MS];
#pragma unroll
    for (int t = 0; t < MS; t++) {
        int c = tid + t * 256;
        int row = c >> 2, seg = c & 3;
        gAp[t] = A2 + (size_t)(tm + row) * KP + seg * 8;
        oA[t] = row * 64 + ((seg ^ (row & 3)) * 16);
    }
    const __nv_bfloat16* gBp[2];
    uint32_t oB[2];
#pragma unroll
    for (int t = 0; t < 2; t++) {
        int c = tid + t * 256;
        int row = c >> 2, seg = c & 3;
        gBp[t] = B2 + (size_t)(tn + row) * KP + seg * 8;
        oB[t] = A_B + row * 64 + ((seg ^ (row & 3)) * 16);
    }

    auto issue_stage = [&](int it) {
        if (it < KITERS) {
            int k0 = it * GBK;
            uint32_t bo = sbase + (it & (STAGES - 1)) * STG;
#pragma unroll
            for (int t = 0; t < MS; t++) CPA16(bo + oA[t], gAp[t] + k0);
#pragma unroll
            for (int t = 0; t < 2; t++) CPA16(bo + oB[t], gBp[t] + k0);
        }
        asm volatile("cp.async.commit_group;");
    };

    float acc[MS][8][4];
#pragma unroll
    for (int i = 0; i < MS; i++)
#pragma unroll
        for (int j = 0; j < 8; j++)
#pragma unroll
            for (int r = 0; r < 4; r++) acc[i][j][r] = 0.0f;

    const int rbase = lane & 15;
    const int kh = lane >> 4;

    issue_stage(0);
    issue_stage(1);
    issue_stage(2);

    for (int it = 0; it < KITERS; ++it) {
        asm volatile("cp.async.wait_group %0;" :: "n"(STAGES - 2));
        __syncthreads();
        issue_stage(it + 3);

        const uint32_t aB = sbase + (it & (STAGES - 1)) * STG;
        const uint32_t bB = aB + A_B;

        // ---- all LDSMs first (both kk halves), then all MMAs ----
        uint32_t a[2][MS][4], b[2][4][4];
#pragma unroll
        for (int kk = 0; kk < 2; kk++) {
            const int segl = kk * 2 + kh;
#pragma unroll
            for (int i = 0; i < MS; i++) {
                int rA = wm + i * 16 + rbase;
                LDSM4(a[kk][i], aB + rA * 64 + ((segl ^ (rA & 3)) * 16));
            }
#pragma unroll
            for (int j2 = 0; j2 < 4; j2++) {
                int rB = wn + j2 * 16 + rbase;
                LDSM4(b[kk][j2], bB + rB * 64 + ((segl ^ (rB & 3)) * 16));
            }
        }
#pragma unroll
        for (int kk = 0; kk < 2; kk++)
#pragma unroll
            for (int i = 0; i < MS; i++)
#pragma unroll
                for (int j = 0; j < 8; j++) {
                    uint32_t b0 = b[kk][j >> 1][(j & 1)];
                    uint32_t b1 = b[kk][j >> 1][(j & 1) + 2];
                    asm volatile(
                        "mma.sync.aligned.m16n8k16.row.col.f32.bf16.bf16.f32 "
                        "{%0,%1,%2,%3}, {%4,%5,%6,%7}, {%8,%9}, {%0,%1,%2,%3};"
                        : "+f"(acc[i][j][0]), "+f"(acc[i][j][1]),
                          "+f"(acc[i][j][2]), "+f"(acc[i][j][3])
                        : "r"(a[kk][i][0]), "r"(a[kk][i][1]),
                          "r"(a[kk][i][2]), "r"(a[kk][i][3]),
                          "r"(b0), "r"(b1));
                }
    }

#pragma unroll
    for (int i = 0; i < MS; i++) {
        int row0 = tm + wm + i * 16 + (lane >> 2);
#pragma unroll
        for (int half = 0; half < 2; half++) {
            int row = row0 + half * 8;
            if (row >= M) continue;
#pragma unroll
            for (int j = 0; j < 8; j++) {
                int col = tn + wn + j * 8 + (lane & 3) * 2;
                float2 v;
                v.x = acc[i][j][half * 2 + 0];
                v.y = acc[i][j][half * 2 + 1];
                if (bias) {
                    float2 bb = *(const float2*)(bias + col);
                    v.x += bb.x; v.y += bb.y;
                }
                *(float2*)(C + (size_t)row * N + col) = v;
            }
        }
    }
}

// ---------------------------------------------------------------------------
// conv_x: x fp32 [M,512] -> A2 split-bf16 [M,1536]  (hi | lo | hi)
// ---------------------------------------------------------------------------
__global__ __launch_bounds__(256)
void conv_x_kernel(const float* __restrict__ x, __nv_bfloat16* __restrict__ A2) {
    size_t i = (size_t)blockIdx.x * blockDim.x + threadIdx.x;
    if (i >= (size_t)MROWS * 128) return;
    size_t row = i >> 7;
    int c4 = (int)(i & 127);
    float4 v = *(const float4*)(x + row * 512 + c4 * 4);
    __nv_bfloat16 h0, h1, h2, h3, l0, l1, l2, l3;
    split_bf16(v.x, h0, l0); split_bf16(v.y, h1, l1);
    split_bf16(v.z, h2, l2); split_bf16(v.w, h3, l3);
    uint2 hp = make_uint2(pack2(h0, h1), pack2(h2, h3));
    uint2 lp = make_uint2(pack2(l0, l1), pack2(l2, l3));
    __nv_bfloat16* base = A2 + row * KP + c4 * 4;
    *(uint2*)(base)        = hp;
    *(uint2*)(base + 512)  = lp;
    *(uint2*)(base + 1024) = hp;
}

// ---------------------------------------------------------------------------
// convW: W fp32 [512,N] -> B2 split-bf16 [N,1536] (transposed, hi | hi | lo)
// ---------------------------------------------------------------------------
__global__ __launch_bounds__(1024)
void convW_kernel(const float* __restrict__ W, __nv_bfloat16* __restrict__ B2, int N) {
    __shared__ float t[32][33];
    int n0 = blockIdx.x * 32, k0 = blockIdx.y * 32;
    int tx = threadIdx.x, ty = threadIdx.y;
    t[ty][tx] = W[(size_t)(k0 + ty) * N + n0 + tx];
    __syncthreads();
    int n = n0 + ty, k = k0 + tx;
    float v = t[tx][ty];
    __nv_bfloat16 h, l;
    split_bf16(v, h, l);
    size_t base = (size_t)n * KP + k;
    B2[base]        = h;
    B2[base + 512]  = h;
    B2[base + 1024] = l;
}

// ---------------------------------------------------------------------------
// Merged attention: blocks [0,512) local attention, [512,544) cls attention.
// Local: single pass, Cauchy-Schwarz bound as softmax max, f32x2 FMA.
// Both write split-bf16 directly.
// ---------------------------------------------------------------------------
__global__ __launch_bounds__(256, 1)
void attn_kernel(const float* __restrict__ qkv, __nv_bfloat16* __restrict__ A2) {
    extern __shared__ float sh[];
    const int tid = threadIdx.x;

    if (blockIdx.x < 512) {
        // ---------------- local attention ----------------
        float* Ks = sh;                 // [197][64]
        float* Vs = sh + NK_ * DH_;     // [197][64]
        __shared__ int s_maxk2;

        const int blk = blockIdx.x;
        const int b = blk / (H_ * F_);
        const int rem = blk % (H_ * F_);
        const int h = rem / F_;
        const int fi = rem % F_;
        const int t0 = 1 + fi * NP_;

        const size_t bbase = (size_t)b * NTOT * QKVC;
        const int hoff = h * DH_;

        if (tid == 0) s_maxk2 = 0;
        for (int idx = tid; idx < NK_ * (DH_ / 4); idx += blockDim.x) {
            int j = idx >> 4;
            int d4 = idx & 15;
            int tok = (j == 0) ? 0 : (t0 + j - 1);
            const float* kp = qkv + bbase + (size_t)tok * QKVC + DIM_ + hoff + d4 * 4;
            *(float4*)&Ks[j * DH_ + d4 * 4] = *(const float4*)kp;
            *(float4*)&Vs[j * DH_ + d4 * 4] = *(const float4*)(kp + DIM_);
        }
        __syncthreads();

        if (tid < NK_) {
            float kn2 = 0.0f;
#pragma unroll
            for (int i = 0; i < 16; i++) {
                float4 kk = *(const float4*)&Ks[tid * DH_ + i * 4];
                kn2 += kk.x * kk.x + kk.y * kk.y + kk.z * kk.z + kk.w * kk.w;
            }
            atomicMax(&s_maxk2, __float_as_int(kn2));
        }
        __syncthreads();
        const float maxk2 = __int_as_float(s_maxk2);

        const int qi = tid;
        if (qi >= NP_) return;
        const int qtok = t0 + qi;
        const float scale = 0.125f;

        const float* qp = qkv + bbase + (size_t)qtok * QKVC + hoff;
        unsigned long long q2[32];
        float qn2 = 0.0f;
#pragma unroll
        for (int i = 0; i < 16; i++) {
            float4 t = *(const float4*)&qp[i * 4];
            float x0 = t.x * scale, x1 = t.y * scale;
            float x2 = t.z * scale, x3 = t.w * scale;
            qn2 += x0 * x0 + x1 * x1 + x2 * x2 + x3 * x3;
            q2[2 * i]     = packf2(x0, x1);
            q2[2 * i + 1] = packf2(x2, x3);
        }
        const float m = sqrtf(qn2 * maxk2) + 1e-6f;

        unsigned long long acc2[32];
#pragma unroll
        for (int i = 0; i < 32; i++) acc2[i] = 0ULL;
        float l = 0.0f;

        for (int j = 0; j < NK_; j++) {
            const unsigned long long* kr = (const unsigned long long*)&Ks[j * DH_];
            unsigned long long s2a = 0ULL, s2b = 0ULL, s2c = 0ULL, s2d = 0ULL;
#pragma unroll
            for (int i = 0; i < 8; i++) {
                s2a = ffma2(q2[4 * i + 0], kr[4 * i + 0], s2a);
                s2b = ffma2(q2[4 * i + 1], kr[4 * i + 1], s2b);
                s2c = ffma2(q2[4 * i + 2], kr[4 * i + 2], s2c);
                s2d = ffma2(q2[4 * i + 3], kr[4 * i + 3], s2d);
            }
            float a0, a1, b0, b1, c0, c1, d0, d1;
            unpackf2(s2a, a0, a1); unpackf2(s2b, b0, b1);
            unpackf2(s2c, c0, c1); unpackf2(s2d, d0, d1);
            float s = ((a0 + a1) + (b0 + b1)) + ((c0 + c1) + (d0 + d1));
            float p = __expf(s - m);
            l += p;
            unsigned long long p2 = packf2(p, p);
            const unsigned long long* vr = (const unsigned long long*)&Vs[j * DH_];
#pragma unroll
            for (int i = 0; i < 32; i++) acc2[i] = ffma2(p2, vr[i], acc2[i]);
        }

        const float inv = 1.0f / l;
        __nv_bfloat16* base = A2 + ((size_t)b * NTOT + qtok) * KP + hoff;
#pragma unroll
        for (int i = 0; i < 16; i++) {
            float v0, v1, v2, v3;
            unpackf2(acc2[2 * i], v0, v1);
            unpackf2(acc2[2 * i + 1], v2, v3);
            v0 *= inv; v1 *= inv; v2 *= inv; v3 *= inv;
            __nv_bfloat16 h0, h1, h2, h3, l0, l1, l2, l3;
            split_bf16(v0, h0, l0); split_bf16(v1, h1, l1);
            split_bf16(v2, h2, l2); split_bf16(v3, h3, l3);
            uint2 hp = make_uint2(pack2(h0, h1), pack2(h2, h3));
            uint2 lp = make_uint2(pack2(l0, l1), pack2(l2, l3));
            *(uint2*)(base + i * 4)        = hp;
            *(uint2*)(base + 512 + i * 4)  = lp;
            *(uint2*)(base + 1024 + i * 4) = hp;
        }
    } else {
        // ---------------- cls attention ----------------
        float* qs     = sh;                    // [64]
        float* sc     = sh + 64;               // [NTOT]
        float* redbuf = sh + 64 + NTOT;        // [8]
        float* accs   = sh + 64 + NTOT + 8;    // [4][64]

        const int cb = blockIdx.x - 512;
        const int b = cb / H_;
        const int h = cb % H_;
        const int lane = tid & 31;
        const int warp = tid >> 5;
        const size_t bbase = (size_t)b * NTOT * QKVC;
        const int hoff = h * DH_;

        if (tid < DH_) qs[tid] = qkv[bbase + hoff + tid] * 0.125f;
        __syncthreads();

        float lmax = -1e30f;
        for (int j = tid; j < NTOT; j += 256) {
            const float* kp = qkv + bbase + (size_t)j * QKVC + DIM_ + hoff;
            float s = 0.0f;
#pragma unroll
            for (int i = 0; i < 16; i++) {
                float4 kk = *(const float4*)&kp[i * 4];
                float4 qq = *(const float4*)&qs[i * 4];
                s += qq.x * kk.x + qq.y * kk.y + qq.z * kk.z + qq.w * kk.w;
            }
            sc[j] = s;
            lmax = fmaxf(lmax, s);
        }
#pragma unroll
        for (int o = 16; o; o >>= 1) lmax = fmaxf(lmax, __shfl_xor_sync(~0u, lmax, o));
        if (lane == 0) redbuf[warp] = lmax;
        __syncthreads();
        float m = fmaxf(fmaxf(fmaxf(redbuf[0], redbuf[1]), fmaxf(redbuf[2], redbuf[3])),
                        fmaxf(fmaxf(redbuf[4], redbuf[5]), fmaxf(redbuf[6], redbuf[7])));
        __syncthreads();

        float lsum = 0.0f;
        for (int j = tid; j < NTOT; j += 256) {
            float p = __expf(sc[j] - m);
            sc[j] = p;
            lsum += p;
        }
#pragma unroll
        for (int o = 16; o; o >>= 1) lsum += __shfl_xor_sync(~0u, lsum, o);
        if (lane == 0) redbuf[warp] = lsum;
        __syncthreads();
        float l = redbuf[0] + redbuf[1] + redbuf[2] + redbuf[3] +
                  redbuf[4] + redbuf[5] + redbuf[6] + redbuf[7];

        const int d = tid & 63;
        const int g = tid >> 6;
        float acc = 0.0f;
        for (int j = g; j < NTOT; j += 4)
            acc += sc[j] * qkv[bbase + (size_t)j * QKVC + 2 * DIM_ + hoff + d];
        accs[g * 64 + d] = acc;
        __syncthreads();
        if (tid < DH_) {
            float o = (accs[0 * 64 + tid] + accs[1 * 64 + tid] +
                       accs[2 * 64 + tid] + accs[3 * 64 + tid]) / l;
            __nv_bfloat16 hh, ll;
            split_bf16(o, hh, ll);
            __nv_bfloat16* base = A2 + (size_t)b * NTOT * KP + hoff + tid;
            base[0]    = hh;
            base[512]  = ll;
            base[1024] = hh;
        }
    }
}

// ---------------------------------------------------------------------------
extern "C" void kernel_launch(void* const* d_in, const int* in_sizes, int n_in,
                              void* d_out, int out_size) {
    const float* x    = (const float*)d_in[0];
    const float* Wqkv = (const float*)d_in[1];
    const float* Wout = (const float*)d_in[2];
    const float* bout = (const float*)d_in[3];
    float* out = (float*)d_out;

    float* qkv = nullptr;
    __nv_bfloat16 *A2x = nullptr, *A2att = nullptr, *B2qkv = nullptr, *B2out = nullptr;
    cudaGetSymbolAddress((void**)&qkv, g_qkv);
    cudaGetSymbolAddress((void**)&A2x, g_A2x);
    cudaGetSymbolAddress((void**)&A2att, g_A2att);
    cudaGetSymbolAddress((void**)&B2qkv, g_B2qkv);
    cudaGetSymbolAddress((void**)&B2out, g_B2out);

    cudaFuncSetAttribute(gemm_mma<4>,
                         cudaFuncAttributeMaxDynamicSharedMemorySize,
                         STAGES * (256 * 64 + 8192));   // 98304
    cudaFuncSetAttribute(gemm_mma<2>,
                         cudaFuncAttributeMaxDynamicSharedMemorySize,
                         STAGES * (128 * 64 + 8192));   // 65536

    // conversions
    {
        size_t tot = (size_t)MROWS * 128;
        conv_x_kernel<<<(unsigned)((tot + 255) / 256), 256>>>(x, A2x);
        convW_kernel<<<dim3(QKVC / 32, DIM_ / 32), dim3(32, 32)>>>(Wqkv, B2qkv, QKVC);
        convW_kernel<<<dim3(DIM_ / 32, DIM_ / 32), dim3(32, 32)>>>(Wout, B2out, DIM_);
    }

    // 1) qkv = x @ W_qkv  (256x128 tiles, 600 CTAs)
    gemm_mma<4><<<dim3(QKVC / 128, 50), 256, STAGES * (256 * 64 + 8192)>>>(
        A2x, B2qkv, nullptr, qkv, MROWS, QKVC);

    // 2) attention: 512 local blocks + 32 cls blocks
    {
        int smem = 2 * NK_ * DH_ * (int)sizeof(float);   // 100864
        cudaFuncSetAttribute(attn_kernel,
                             cudaFuncAttributeMaxDynamicSharedMemorySize, smem);
        attn_kernel<<<B_ * H_ * F_ + B_ * H_, 256, smem>>>(qkv, A2att);
    }

    // 3) out = att @ W_out + b_out  (128x128 tiles, 396 CTAs)
    gemm_mma<2><<<dim3(DIM_ / 128, 99), 256, STAGES * (128 * 64 + 8192)>>>(
        A2att, B2out, bout, out, MROWS, DIM_);
}

// round 13
// speedup vs baseline: 2.3188x; 1.0740x over previous
#include <cuda_runtime.h>
#include <cuda_bf16.h>
#include <cstdint>

// Problem constants
#define B_   4
#define F_   16
#define NP_  196
#define DIM_ 512
#define H_   8
#define DH_  64
#define NTOT 3137            // 1 + F*NP
#define MROWS (B_ * NTOT)    // 12548
#define MPAD  12800          // 50 * 256 (covers 99*128=12672)
#define QKVC (3 * H_ * DH_)  // 1536
#define NK_  197             // cls + 196 local keys
#define KP   1536            // split-bf16 K' = 3*512

// ---------------------------------------------------------------------------
// Scratch (allocation-free: __device__ globals)
// ---------------------------------------------------------------------------
__device__ float         g_qkv[(size_t)MROWS * QKVC];
__device__ __nv_bfloat16 g_A2x[(size_t)MPAD * KP];
__device__ __nv_bfloat16 g_A2att[(size_t)MPAD * KP];
__device__ __nv_bfloat16 g_B2qkv[(size_t)QKVC * KP];
__device__ __nv_bfloat16 g_B2out[(size_t)DIM_ * KP];

// ---------------------------------------------------------------------------
__device__ __forceinline__ uint32_t smem_to_u32(const void* p) {
    uint32_t a;
    asm("{ .reg .u64 t; cvta.to.shared.u64 t, %1; cvt.u32.u64 %0, t; }"
        : "=r"(a) : "l"(p));
    return a;
}

__device__ __forceinline__ void split_bf16(float v, __nv_bfloat16& h, __nv_bfloat16& l) {
    h = __float2bfloat16_rn(v);
    l = __float2bfloat16_rn(v - __bfloat162float(h));
}
__device__ __forceinline__ uint32_t pack2(__nv_bfloat16 a, __nv_bfloat16 b) {
    __nv_bfloat162 t = __halves2bfloat162(a, b);
    return *(uint32_t*)&t;
}

// packed f32x2 helpers (sm_100+)
__device__ __forceinline__ unsigned long long ffma2(unsigned long long a,
                                                    unsigned long long b,
                                                    unsigned long long c) {
    unsigned long long d;
    asm("fma.rn.f32x2 %0, %1, %2, %3;" : "=l"(d) : "l"(a), "l"(b), "l"(c));
    return d;
}
__device__ __forceinline__ unsigned long long packf2(float x, float y) {
    unsigned long long r;
    asm("mov.b64 %0, {%1, %2};" : "=l"(r) : "f"(x), "f"(y));
    return r;
}
__device__ __forceinline__ void unpackf2(unsigned long long r, float& x, float& y) {
    asm("mov.b64 {%0, %1}, %2;" : "=f"(x), "=f"(y) : "l"(r));
}

#define LDSM4(r, addr) \
    asm volatile("ldmatrix.sync.aligned.m8n8.x4.shared.b16 {%0,%1,%2,%3}, [%4];" \
                 : "=r"((r)[0]), "=r"((r)[1]), "=r"((r)[2]), "=r"((r)[3]) \
                 : "r"(addr))
#define CPA16(dst, src) \
    asm volatile("cp.async.cg.shared.global [%0], [%1], 16;" :: "r"(dst), "l"(src))

// ---------------------------------------------------------------------------
// HMMA GEMM: C[M,N] = A2[M,KP] . B2[N,KP]^T (+ bias).
// BK=64: smem rows are 128B with seg^(row&7) swizzle -> ldmatrix is
// bank-conflict-FREE (the old 64B-row layout had a 2-way conflict).
// Template: MS = m16 subtiles per warp (4 -> 256x128 CTA tile, 2 -> 128x128),
// NSTG = pipeline stages, MINB = min blocks/SM for launch_bounds.
// 8 warps 4(m)x2(n); one __syncthreads per K-iter (24 iters).
// ---------------------------------------------------------------------------
#define BK2 64
#define KIT2 (KP / BK2)            // 24

template <int MS, int NSTG, int MINB>
__global__ __launch_bounds__(256, MINB)
void gemm_mma(const __nv_bfloat16* __restrict__ A2,
              const __nv_bfloat16* __restrict__ B2,
              const float* __restrict__ bias,
              float* __restrict__ C, int M, int N) {
    constexpr int GBMt = MS * 64;
    constexpr int A_B  = GBMt * 128;           // A bytes per stage
    constexpr int STG  = A_B + 128 * 128;      // + B tile (128 rows x 128B)
    extern __shared__ __align__(128) unsigned char smem[];

    const int tid  = threadIdx.x;
    const int wid  = tid >> 5;
    const int lane = tid & 31;
    const int wm = (wid & 3) * (MS * 16);
    const int wn = (wid >> 2) * 64;
    const int tm = blockIdx.y * GBMt;
    const int tn = blockIdx.x * 128;

    const uint32_t sbase = smem_to_u32(smem);

    // copy plan: chunk c = tid + t*256 -> row = c>>3 (= row0 + 32t), seg = tid&7
    // (seg is t-invariant since 256 % 8 == 0), so everything derives from one
    // base pointer / offset plus compile-time constants.
    const int row0 = tid >> 3;
    const int seg  = tid & 7;
    const __nv_bfloat16* gA0 = A2 + (size_t)(tm + row0) * KP + seg * 8;
    const __nv_bfloat16* gB0 = B2 + (size_t)(tn + row0) * KP + seg * 8;
    const uint32_t oA0 = row0 * 128 + ((seg ^ (row0 & 7)) * 16);
    const uint32_t oB0 = A_B + oA0;

    auto issue_stage = [&](int it) {
        if (it < KIT2) {
            int k0 = it * BK2;
            uint32_t bo = sbase + (it % NSTG) * STG;
#pragma unroll
            for (int t = 0; t < MS * 2; t++)
                CPA16(bo + oA0 + t * 4096, gA0 + (size_t)t * 32 * KP + k0);
#pragma unroll
            for (int t = 0; t < 4; t++)
                CPA16(bo + oB0 + t * 4096, gB0 + (size_t)t * 32 * KP + k0);
        }
        asm volatile("cp.async.commit_group;");
    };

    float acc[MS][8][4];
#pragma unroll
    for (int i = 0; i < MS; i++)
#pragma unroll
        for (int j = 0; j < 8; j++)
#pragma unroll
            for (int r = 0; r < 4; r++) acc[i][j][r] = 0.0f;

    const int rbase = lane & 15;
    const int kh = lane >> 4;

#pragma unroll
    for (int s = 0; s < NSTG - 1; s++) issue_stage(s);

    for (int it = 0; it < KIT2; ++it) {
        asm volatile("cp.async.wait_group %0;" :: "n"(NSTG - 2));
        __syncthreads();
        issue_stage(it + NSTG - 1);

        const uint32_t aB = sbase + (it % NSTG) * STG;
        const uint32_t bB = aB + A_B;

#pragma unroll
        for (int kk = 0; kk < 4; kk++) {
            const int segl = kk * 2 + kh;
            uint32_t a[MS][4];
#pragma unroll
            for (int i = 0; i < MS; i++) {
                int rA = wm + i * 16 + rbase;
                LDSM4(a[i], aB + rA * 128 + ((segl ^ (rA & 7)) * 16));
            }
            uint32_t b[4][4];
#pragma unroll
            for (int j2 = 0; j2 < 4; j2++) {
                int rB = wn + j2 * 16 + rbase;
                LDSM4(b[j2], bB + rB * 128 + ((segl ^ (rB & 7)) * 16));
            }
#pragma unroll
            for (int i = 0; i < MS; i++)
#pragma unroll
                for (int j = 0; j < 8; j++) {
                    uint32_t b0 = b[j >> 1][(j & 1)];
                    uint32_t b1 = b[j >> 1][(j & 1) + 2];
                    asm volatile(
                        "mma.sync.aligned.m16n8k16.row.col.f32.bf16.bf16.f32 "
                        "{%0,%1,%2,%3}, {%4,%5,%6,%7}, {%8,%9}, {%0,%1,%2,%3};"
                        : "+f"(acc[i][j][0]), "+f"(acc[i][j][1]),
                          "+f"(acc[i][j][2]), "+f"(acc[i][j][3])
                        : "r"(a[i][0]), "r"(a[i][1]), "r"(a[i][2]), "r"(a[i][3]),
                          "r"(b0), "r"(b1));
                }
        }
    }

#pragma unroll
    for (int i = 0; i < MS; i++) {
        int row0e = tm + wm + i * 16 + (lane >> 2);
#pragma unroll
        for (int half = 0; half < 2; half++) {
            int row = row0e + half * 8;
            if (row >= M) continue;
#pragma unroll
            for (int j = 0; j < 8; j++) {
                int col = tn + wn + j * 8 + (lane & 3) * 2;
                float2 v;
                v.x = acc[i][j][half * 2 + 0];
                v.y = acc[i][j][half * 2 + 1];
                if (bias) {
                    float2 bb = *(const float2*)(bias + col);
                    v.x += bb.x; v.y += bb.y;
                }
                *(float2*)(C + (size_t)row * N + col) = v;
            }
        }
    }
}

// ---------------------------------------------------------------------------
// conv_x: x fp32 [M,512] -> A2 split-bf16 [M,1536]  (hi | lo | hi)
// ---------------------------------------------------------------------------
__global__ __launch_bounds__(256)
void conv_x_kernel(const float* __restrict__ x, __nv_bfloat16* __restrict__ A2) {
    size_t i = (size_t)blockIdx.x * blockDim.x + threadIdx.x;
    if (i >= (size_t)MROWS * 128) return;
    size_t row = i >> 7;
    int c4 = (int)(i & 127);
    float4 v = *(const float4*)(x + row * 512 + c4 * 4);
    __nv_bfloat16 h0, h1, h2, h3, l0, l1, l2, l3;
    split_bf16(v.x, h0, l0); split_bf16(v.y, h1, l1);
    split_bf16(v.z, h2, l2); split_bf16(v.w, h3, l3);
    uint2 hp = make_uint2(pack2(h0, h1), pack2(h2, h3));
    uint2 lp = make_uint2(pack2(l0, l1), pack2(l2, l3));
    __nv_bfloat16* base = A2 + row * KP + c4 * 4;
    *(uint2*)(base)        = hp;
    *(uint2*)(base + 512)  = lp;
    *(uint2*)(base + 1024) = hp;
}

// ---------------------------------------------------------------------------
// convW: W fp32 [512,N] -> B2 split-bf16 [N,1536] (transposed, hi | hi | lo)
// ---------------------------------------------------------------------------
__global__ __launch_bounds__(1024)
void convW_kernel(const float* __restrict__ W, __nv_bfloat16* __restrict__ B2, int N) {
    __shared__ float t[32][33];
    int n0 = blockIdx.x * 32, k0 = blockIdx.y * 32;
    int tx = threadIdx.x, ty = threadIdx.y;
    t[ty][tx] = W[(size_t)(k0 + ty) * N + n0 + tx];
    __syncthreads();
    int n = n0 + ty, k = k0 + tx;
    float v = t[tx][ty];
    __nv_bfloat16 h, l;
    split_bf16(v, h, l);
    size_t base = (size_t)n * KP + k;
    B2[base]        = h;
    B2[base + 512]  = h;
    B2[base + 1024] = l;
}

// ---------------------------------------------------------------------------
// Merged attention: blocks [0,512) local, [512,544) cls. Writes split-bf16.
// ---------------------------------------------------------------------------
__global__ __launch_bounds__(256, 1)
void attn_kernel(const float* __restrict__ qkv, __nv_bfloat16* __restrict__ A2) {
    extern __shared__ float sh[];
    const int tid = threadIdx.x;

    if (blockIdx.x < 512) {
        float* Ks = sh;
        float* Vs = sh + NK_ * DH_;
        __shared__ int s_maxk2;

        const int blk = blockIdx.x;
        const int b = blk / (H_ * F_);
        const int rem = blk % (H_ * F_);
        const int h = rem / F_;
        const int fi = rem % F_;
        const int t0 = 1 + fi * NP_;

        const size_t bbase = (size_t)b * NTOT * QKVC;
        const int hoff = h * DH_;

        if (tid == 0) s_maxk2 = 0;
        for (int idx = tid; idx < NK_ * (DH_ / 4); idx += blockDim.x) {
            int j = idx >> 4;
            int d4 = idx & 15;
            int tok = (j == 0) ? 0 : (t0 + j - 1);
            const float* kp = qkv + bbase + (size_t)tok * QKVC + DIM_ + hoff + d4 * 4;
            *(float4*)&Ks[j * DH_ + d4 * 4] = *(const float4*)kp;
            *(float4*)&Vs[j * DH_ + d4 * 4] = *(const float4*)(kp + DIM_);
        }
        __syncthreads();

        if (tid < NK_) {
            float kn2 = 0.0f;
#pragma unroll
            for (int i = 0; i < 16; i++) {
                float4 kk = *(const float4*)&Ks[tid * DH_ + i * 4];
                kn2 += kk.x * kk.x + kk.y * kk.y + kk.z * kk.z + kk.w * kk.w;
            }
            atomicMax(&s_maxk2, __float_as_int(kn2));
        }
        __syncthreads();
        const float maxk2 = __int_as_float(s_maxk2);

        const int qi = tid;
        if (qi >= NP_) return;
        const int qtok = t0 + qi;
        const float scale = 0.125f;

        const float* qp = qkv + bbase + (size_t)qtok * QKVC + hoff;
        unsigned long long q2[32];
        float qn2 = 0.0f;
#pragma unroll
        for (int i = 0; i < 16; i++) {
            float4 t = *(const float4*)&qp[i * 4];
            float x0 = t.x * scale, x1 = t.y * scale;
            float x2 = t.z * scale, x3 = t.w * scale;
            qn2 += x0 * x0 + x1 * x1 + x2 * x2 + x3 * x3;
            q2[2 * i]     = packf2(x0, x1);
            q2[2 * i + 1] = packf2(x2, x3);
        }
        const float m = sqrtf(qn2 * maxk2) + 1e-6f;

        unsigned long long acc2[32];
#pragma unroll
        for (int i = 0; i < 32; i++) acc2[i] = 0ULL;
        float l = 0.0f;

        for (int j = 0; j < NK_; j++) {
            const unsigned long long* kr = (const unsigned long long*)&Ks[j * DH_];
            unsigned long long s2a = 0ULL, s2b = 0ULL, s2c = 0ULL, s2d = 0ULL;
#pragma unroll
            for (int i = 0; i < 8; i++) {
                s2a = ffma2(q2[4 * i + 0], kr[4 * i + 0], s2a);
                s2b = ffma2(q2[4 * i + 1], kr[4 * i + 1], s2b);
                s2c = ffma2(q2[4 * i + 2], kr[4 * i + 2], s2c);
                s2d = ffma2(q2[4 * i + 3], kr[4 * i + 3], s2d);
            }
            float a0, a1, b0, b1, c0, c1, d0, d1;
            unpackf2(s2a, a0, a1); unpackf2(s2b, b0, b1);
            unpackf2(s2c, c0, c1); unpackf2(s2d, d0, d1);
            float s = ((a0 + a1) + (b0 + b1)) + ((c0 + c1) + (d0 + d1));
            float p = __expf(s - m);
            l += p;
            unsigned long long p2 = packf2(p, p);
            const unsigned long long* vr = (const unsigned long long*)&Vs[j * DH_];
#pragma unroll
            for (int i = 0; i < 32; i++) acc2[i] = ffma2(p2, vr[i], acc2[i]);
        }

        const float inv = 1.0f / l;
        __nv_bfloat16* base = A2 + ((size_t)b * NTOT + qtok) * KP + hoff;
#pragma unroll
        for (int i = 0; i < 16; i++) {
            float v0, v1, v2, v3;
            unpackf2(acc2[2 * i], v0, v1);
            unpackf2(acc2[2 * i + 1], v2, v3);
            v0 *= inv; v1 *= inv; v2 *= inv; v3 *= inv;
            __nv_bfloat16 h0, h1, h2, h3, l0, l1, l2, l3;
            split_bf16(v0, h0, l0); split_bf16(v1, h1, l1);
            split_bf16(v2, h2, l2); split_bf16(v3, h3, l3);
            uint2 hp = make_uint2(pack2(h0, h1), pack2(h2, h3));
            uint2 lp = make_uint2(pack2(l0, l1), pack2(l2, l3));
            *(uint2*)(base + i * 4)        = hp;
            *(uint2*)(base + 512 + i * 4)  = lp;
            *(uint2*)(base + 1024 + i * 4) = hp;
        }
    } else {
        float* qs     = sh;
        float* sc     = sh + 64;
        float* redbuf = sh + 64 + NTOT;
        float* accs   = sh + 64 + NTOT + 8;

        const int cb = blockIdx.x - 512;
        const int b = cb / H_;
        const int h = cb % H_;
        const int lane = tid & 31;
        const int warp = tid >> 5;
        const size_t bbase = (size_t)b * NTOT * QKVC;
        const int hoff = h * DH_;

        if (tid < DH_) qs[tid] = qkv[bbase + hoff + tid] * 0.125f;
        __syncthreads();

        float lmax = -1e30f;
        for (int j = tid; j < NTOT; j += 256) {
            const float* kp = qkv + bbase + (size_t)j * QKVC + DIM_ + hoff;
            float s = 0.0f;
#pragma unroll
            for (int i = 0; i < 16; i++) {
                float4 kk = *(const float4*)&kp[i * 4];
                float4 qq = *(const float4*)&qs[i * 4];
                s += qq.x * kk.x + qq.y * kk.y + qq.z * kk.z + qq.w * kk.w;
            }
            sc[j] = s;
            lmax = fmaxf(lmax, s);
        }
#pragma unroll
        for (int o = 16; o; o >>= 1) lmax = fmaxf(lmax, __shfl_xor_sync(~0u, lmax, o));
        if (lane == 0) redbuf[warp] = lmax;
        __syncthreads();
        float m = fmaxf(fmaxf(fmaxf(redbuf[0], redbuf[1]), fmaxf(redbuf[2], redbuf[3])),
                        fmaxf(fmaxf(redbuf[4], redbuf[5]), fmaxf(redbuf[6], redbuf[7])));
        __syncthreads();

        float lsum = 0.0f;
        for (int j = tid; j < NTOT; j += 256) {
            float p = __expf(sc[j] - m);
            sc[j] = p;
            lsum += p;
        }
#pragma unroll
        for (int o = 16; o; o >>= 1) lsum += __shfl_xor_sync(~0u, lsum, o);
        if (lane == 0) redbuf[warp] = lsum;
        __syncthreads();
        float l = redbuf[0] + redbuf[1] + redbuf[2] + redbuf[3] +
                  redbuf[4] + redbuf[5] + redbuf[6] + redbuf[7];

        const int d = tid & 63;
        const int g = tid >> 6;
        float acc = 0.0f;
        for (int j = g; j < NTOT; j += 4)
            acc += sc[j] * qkv[bbase + (size_t)j * QKVC + 2 * DIM_ + hoff + d];
        accs[g * 64 + d] = acc;
        __syncthreads();
        if (tid < DH_) {
            float o = (accs[0 * 64 + tid] + accs[1 * 64 + tid] +
                       accs[2 * 64 + tid] + accs[3 * 64 + tid]) / l;
            __nv_bfloat16 hh, ll;
            split_bf16(o, hh, ll);
            __nv_bfloat16* base = A2 + (size_t)b * NTOT * KP + hoff + tid;
            base[0]    = hh;
            base[512]  = ll;
            base[1024] = hh;
        }
    }
}

// ---------------------------------------------------------------------------
extern "C" void kernel_launch(void* const* d_in, const int* in_sizes, int n_in,
                              void* d_out, int out_size) {
    const float* x    = (const float*)d_in[0];
    const float* Wqkv = (const float*)d_in[1];
    const float* Wout = (const float*)d_in[2];
    const float* bout = (const float*)d_in[3];
    float* out = (float*)d_out;

    float* qkv = nullptr;
    __nv_bfloat16 *A2x = nullptr, *A2att = nullptr, *B2qkv = nullptr, *B2out = nullptr;
    cudaGetSymbolAddress((void**)&qkv, g_qkv);
    cudaGetSymbolAddress((void**)&A2x, g_A2x);
    cudaGetSymbolAddress((void**)&A2att, g_A2att);
    cudaGetSymbolAddress((void**)&B2qkv, g_B2qkv);
    cudaGetSymbolAddress((void**)&B2out, g_B2out);

    // gemm<4,4,1>: stage = 256*128 + 128*128 = 48KB, 4 stages = 192KB, 1 CTA/SM
    constexpr int SM_BIG = 4 * (256 * 128 + 128 * 128);
    // gemm<2,3,2>: stage = 128*128 + 128*128 = 32KB, 3 stages = 96KB, 2 CTA/SM
    constexpr int SM_SML = 3 * (128 * 128 + 128 * 128);

    cudaFuncSetAttribute((const void*)&gemm_mma<4, 4, 1>,
                         cudaFuncAttributeMaxDynamicSharedMemorySize, SM_BIG);
    cudaFuncSetAttribute((const void*)&gemm_mma<2, 3, 2>,
                         cudaFuncAttributeMaxDynamicSharedMemorySize, SM_SML);

    // conversions
    {
        size_t tot = (size_t)MROWS * 128;
        conv_x_kernel<<<(unsigned)((tot + 255) / 256), 256>>>(x, A2x);
        convW_kernel<<<dim3(QKVC / 32, DIM_ / 32), dim3(32, 32)>>>(Wqkv, B2qkv, QKVC);
        convW_kernel<<<dim3(DIM_ / 32, DIM_ / 32), dim3(32, 32)>>>(Wout, B2out, DIM_);
    }

    // 1) qkv = x @ W_qkv  (256x128 tiles, 600 CTAs)
    gemm_mma<4, 4, 1><<<dim3(QKVC / 128, 50), 256, SM_BIG>>>(
        A2x, B2qkv, nullptr, qkv, MROWS, QKVC);

    // 2) attention: 512 local blocks + 32 cls blocks
    {
        int smem = 2 * NK_ * DH_ * (int)sizeof(float);   // 100864
        cudaFuncSetAttribute(attn_kernel,
                             cudaFuncAttributeMaxDynamicSharedMemorySize, smem);
        attn_kernel<<<B_ * H_ * F_ + B_ * H_, 256, smem>>>(qkv, A2att);
    }

    // 3) out = att @ W_out + b_out  (128x128 tiles, 396 CTAs, 2 CTA/SM)
    gemm_mma<2, 3, 2><<<dim3(DIM_ / 128, 99), 256, SM_SML>>>(
        A2att, B2out, bout, out, MROWS, DIM_);
}

// round 14
// speedup vs baseline: 2.3470x; 1.0121x over previous
#include <cuda_runtime.h>
#include <cuda_bf16.h>
#include <cstdint>

// Problem constants
#define B_   4
#define F_   16
#define NP_  196
#define DIM_ 512
#define H_   8
#define DH_  64
#define NTOT 3137            // 1 + F*NP
#define MROWS (B_ * NTOT)    // 12548
#define MPAD  12800          // 50 * 256 (covers 198*64=12672)
#define QKVC (3 * H_ * DH_)  // 1536
#define NK_  197             // cls + 196 local keys
#define KP   1536            // split-bf16 K' = 3*512

// ---------------------------------------------------------------------------
// Scratch (allocation-free: __device__ globals)
// ---------------------------------------------------------------------------
__device__ float         g_qkv[(size_t)MROWS * QKVC];
__device__ __nv_bfloat16 g_A2x[(size_t)MPAD * KP];
__device__ __nv_bfloat16 g_A2att[(size_t)MPAD * KP];
__device__ __nv_bfloat16 g_B2qkv[(size_t)QKVC * KP];
__device__ __nv_bfloat16 g_B2out[(size_t)DIM_ * KP];

// ---------------------------------------------------------------------------
__device__ __forceinline__ uint32_t smem_to_u32(const void* p) {
    uint32_t a;
    asm("{ .reg .u64 t; cvta.to.shared.u64 t, %1; cvt.u32.u64 %0, t; }"
        : "=r"(a) : "l"(p));
    return a;
}

__device__ __forceinline__ void split_bf16(float v, __nv_bfloat16& h, __nv_bfloat16& l) {
    h = __float2bfloat16_rn(v);
    l = __float2bfloat16_rn(v - __bfloat162float(h));
}
__device__ __forceinline__ uint32_t pack2(__nv_bfloat16 a, __nv_bfloat16 b) {
    __nv_bfloat162 t = __halves2bfloat162(a, b);
    return *(uint32_t*)&t;
}

// packed f32x2 helpers (sm_100+)
__device__ __forceinline__ unsigned long long ffma2(unsigned long long a,
                                                    unsigned long long b,
                                                    unsigned long long c) {
    unsigned long long d;
    asm("fma.rn.f32x2 %0, %1, %2, %3;" : "=l"(d) : "l"(a), "l"(b), "l"(c));
    return d;
}
__device__ __forceinline__ unsigned long long packf2(float x, float y) {
    unsigned long long r;
    asm("mov.b64 %0, {%1, %2};" : "=l"(r) : "f"(x), "f"(y));
    return r;
}
__device__ __forceinline__ void unpackf2(unsigned long long r, float& x, float& y) {
    asm("mov.b64 {%0, %1}, %2;" : "=f"(x), "=f"(y) : "l"(r));
}

#define LDSM4(r, addr) \
    asm volatile("ldmatrix.sync.aligned.m8n8.x4.shared.b16 {%0,%1,%2,%3}, [%4];" \
                 : "=r"((r)[0]), "=r"((r)[1]), "=r"((r)[2]), "=r"((r)[3]) \
                 : "r"(addr))
#define CPA16(dst, src) \
    asm volatile("cp.async.cg.shared.global [%0], [%1], 16;" :: "r"(dst), "l"(src))

// ---------------------------------------------------------------------------
// HMMA GEMM: C[M,N] = A2[M,KP] . B2[N,KP]^T (+ bias).
// BK=64, 128B smem rows, seg^(row&7) swizzle -> conflict-free ldmatrix.
// MS = m16 subtiles per warp (4 -> 256x128 CTA, 2 -> 128x128, 1 -> 64x128),
// NSTG = pipeline stages, MINB = min blocks/SM. 8 warps 4(m)x2(n).
// ---------------------------------------------------------------------------
#define BK2 64
#define KIT2 (KP / BK2)            // 24

template <int MS, int NSTG, int MINB>
__global__ __launch_bounds__(256, MINB)
void gemm_mma(const __nv_bfloat16* __restrict__ A2,
              const __nv_bfloat16* __restrict__ B2,
              const float* __restrict__ bias,
              float* __restrict__ C, int M, int N) {
    constexpr int GBMt = MS * 64;
    constexpr int A_B  = GBMt * 128;           // A bytes per stage
    constexpr int STG  = A_B + 128 * 128;      // + B tile
    extern __shared__ __align__(128) unsigned char smem[];

    const int tid  = threadIdx.x;
    const int wid  = tid >> 5;
    const int lane = tid & 31;
    const int wm = (wid & 3) * (MS * 16);
    const int wn = (wid >> 2) * 64;
    const int tm = blockIdx.y * GBMt;
    const int tn = blockIdx.x * 128;

    const uint32_t sbase = smem_to_u32(smem);

    const int row0 = tid >> 3;
    const int seg  = tid & 7;
    const __nv_bfloat16* gA0 = A2 + (size_t)(tm + row0) * KP + seg * 8;
    const __nv_bfloat16* gB0 = B2 + (size_t)(tn + row0) * KP + seg * 8;
    const uint32_t oA0 = row0 * 128 + ((seg ^ (row0 & 7)) * 16);
    const uint32_t oB0 = A_B + oA0;

    auto issue_stage = [&](int it) {
        if (it < KIT2) {
            int k0 = it * BK2;
            uint32_t bo = sbase + (it % NSTG) * STG;
#pragma unroll
            for (int t = 0; t < MS * 2; t++)
                CPA16(bo + oA0 + t * 4096, gA0 + (size_t)t * 32 * KP + k0);
#pragma unroll
            for (int t = 0; t < 4; t++)
                CPA16(bo + oB0 + t * 4096, gB0 + (size_t)t * 32 * KP + k0);
        }
        asm volatile("cp.async.commit_group;");
    };

    float acc[MS][8][4];
#pragma unroll
    for (int i = 0; i < MS; i++)
#pragma unroll
        for (int j = 0; j < 8; j++)
#pragma unroll
            for (int r = 0; r < 4; r++) acc[i][j][r] = 0.0f;

    const int rbase = lane & 15;
    const int kh = lane >> 4;

#pragma unroll
    for (int s = 0; s < NSTG - 1; s++) issue_stage(s);

    for (int it = 0; it < KIT2; ++it) {
        asm volatile("cp.async.wait_group %0;" :: "n"(NSTG - 2));
        __syncthreads();
        issue_stage(it + NSTG - 1);

        const uint32_t aB = sbase + (it % NSTG) * STG;
        const uint32_t bB = aB + A_B;

#pragma unroll
        for (int kk = 0; kk < 4; kk++) {
            const int segl = kk * 2 + kh;
            uint32_t a[MS][4];
#pragma unroll
            for (int i = 0; i < MS; i++) {
                int rA = wm + i * 16 + rbase;
                LDSM4(a[i], aB + rA * 128 + ((segl ^ (rA & 7)) * 16));
            }
            uint32_t b[4][4];
#pragma unroll
            for (int j2 = 0; j2 < 4; j2++) {
                int rB = wn + j2 * 16 + rbase;
                LDSM4(b[j2], bB + rB * 128 + ((segl ^ (rB & 7)) * 16));
            }
#pragma unroll
            for (int i = 0; i < MS; i++)
#pragma unroll
                for (int j = 0; j < 8; j++) {
                    uint32_t b0 = b[j >> 1][(j & 1)];
                    uint32_t b1 = b[j >> 1][(j & 1) + 2];
                    asm volatile(
                        "mma.sync.aligned.m16n8k16.row.col.f32.bf16.bf16.f32 "
                        "{%0,%1,%2,%3}, {%4,%5,%6,%7}, {%8,%9}, {%0,%1,%2,%3};"
                        : "+f"(acc[i][j][0]), "+f"(acc[i][j][1]),
                          "+f"(acc[i][j][2]), "+f"(acc[i][j][3])
                        : "r"(a[i][0]), "r"(a[i][1]), "r"(a[i][2]), "r"(a[i][3]),
                          "r"(b0), "r"(b1));
                }
        }
    }

#pragma unroll
    for (int i = 0; i < MS; i++) {
        int row0e = tm + wm + i * 16 + (lane >> 2);
#pragma unroll
        for (int half = 0; half < 2; half++) {
            int row = row0e + half * 8;
            if (row >= M) continue;
#pragma unroll
            for (int j = 0; j < 8; j++) {
                int col = tn + wn + j * 8 + (lane & 3) * 2;
                float2 v;
                v.x = acc[i][j][half * 2 + 0];
                v.y = acc[i][j][half * 2 + 1];
                if (bias) {
                    float2 bb = *(const float2*)(bias + col);
                    v.x += bb.x; v.y += bb.y;
                }
                *(float2*)(C + (size_t)row * N + col) = v;
            }
        }
    }
}

// ---------------------------------------------------------------------------
// conv_x: x fp32 [M,512] -> A2 split-bf16 [M,1536]  (hi | lo | hi)
// ---------------------------------------------------------------------------
__global__ __launch_bounds__(256)
void conv_x_kernel(const float* __restrict__ x, __nv_bfloat16* __restrict__ A2) {
    size_t i = (size_t)blockIdx.x * blockDim.x + threadIdx.x;
    if (i >= (size_t)MROWS * 128) return;
    size_t row = i >> 7;
    int c4 = (int)(i & 127);
    float4 v = *(const float4*)(x + row * 512 + c4 * 4);
    __nv_bfloat16 h0, h1, h2, h3, l0, l1, l2, l3;
    split_bf16(v.x, h0, l0); split_bf16(v.y, h1, l1);
    split_bf16(v.z, h2, l2); split_bf16(v.w, h3, l3);
    uint2 hp = make_uint2(pack2(h0, h1), pack2(h2, h3));
    uint2 lp = make_uint2(pack2(l0, l1), pack2(l2, l3));
    __nv_bfloat16* base = A2 + row * KP + c4 * 4;
    *(uint2*)(base)        = hp;
    *(uint2*)(base + 512)  = lp;
    *(uint2*)(base + 1024) = hp;
}

// ---------------------------------------------------------------------------
// convW: W fp32 [512,N] -> B2 split-bf16 [N,1536] (transposed, hi | hi | lo)
// ---------------------------------------------------------------------------
__global__ __launch_bounds__(1024)
void convW_kernel(const float* __restrict__ W, __nv_bfloat16* __restrict__ B2, int N) {
    __shared__ float t[32][33];
    int n0 = blockIdx.x * 32, k0 = blockIdx.y * 32;
    int tx = threadIdx.x, ty = threadIdx.y;
    t[ty][tx] = W[(size_t)(k0 + ty) * N + n0 + tx];
    __syncthreads();
    int n = n0 + ty, k = k0 + tx;
    float v = t[tx][ty];
    __nv_bfloat16 h, l;
    split_bf16(v, h, l);
    size_t base = (size_t)n * KP + k;
    B2[base]        = h;
    B2[base + 512]  = h;
    B2[base + 1024] = l;
}

// ---------------------------------------------------------------------------
// Merged attention: blocks [0,512) local, [512,544) cls. Writes split-bf16.
// Local loop uses LDS.128 (ulonglong2) K/V reads: 32 shared loads per key
// instead of 64 -> ~23% fewer issue slots in the issue-bound mainloop.
// ---------------------------------------------------------------------------
__global__ __launch_bounds__(256, 1)
void attn_kernel(const float* __restrict__ qkv, __nv_bfloat16* __restrict__ A2) {
    extern __shared__ float sh[];
    const int tid = threadIdx.x;

    if (blockIdx.x < 512) {
        float* Ks = sh;
        float* Vs = sh + NK_ * DH_;
        __shared__ int s_maxk2;

        const int blk = blockIdx.x;
        const int b = blk / (H_ * F_);
        const int rem = blk % (H_ * F_);
        const int h = rem / F_;
        const int fi = rem % F_;
        const int t0 = 1 + fi * NP_;

        const size_t bbase = (size_t)b * NTOT * QKVC;
        const int hoff = h * DH_;

        if (tid == 0) s_maxk2 = 0;
        for (int idx = tid; idx < NK_ * (DH_ / 4); idx += blockDim.x) {
            int j = idx >> 4;
            int d4 = idx & 15;
            int tok = (j == 0) ? 0 : (t0 + j - 1);
            const float* kp = qkv + bbase + (size_t)tok * QKVC + DIM_ + hoff + d4 * 4;
            *(float4*)&Ks[j * DH_ + d4 * 4] = *(const float4*)kp;
            *(float4*)&Vs[j * DH_ + d4 * 4] = *(const float4*)(kp + DIM_);
        }
        __syncthreads();

        if (tid < NK_) {
            float kn2 = 0.0f;
#pragma unroll
            for (int i = 0; i < 16; i++) {
                float4 kk = *(const float4*)&Ks[tid * DH_ + i * 4];
                kn2 += kk.x * kk.x + kk.y * kk.y + kk.z * kk.z + kk.w * kk.w;
            }
            atomicMax(&s_maxk2, __float_as_int(kn2));
        }
        __syncthreads();
        const float maxk2 = __int_as_float(s_maxk2);

        const int qi = tid;
        if (qi >= NP_) return;
        const int qtok = t0 + qi;
        const float scale = 0.125f;

        const float* qp = qkv + bbase + (size_t)qtok * QKVC + hoff;
        unsigned long long q2[32];
        float qn2 = 0.0f;
#pragma unroll
        for (int i = 0; i < 16; i++) {
            float4 t = *(const float4*)&qp[i * 4];
            float x0 = t.x * scale, x1 = t.y * scale;
            float x2 = t.z * scale, x3 = t.w * scale;
            qn2 += x0 * x0 + x1 * x1 + x2 * x2 + x3 * x3;
            q2[2 * i]     = packf2(x0, x1);
            q2[2 * i + 1] = packf2(x2, x3);
        }
        const float m = sqrtf(qn2 * maxk2) + 1e-6f;

        unsigned long long acc2[32];
#pragma unroll
        for (int i = 0; i < 32; i++) acc2[i] = 0ULL;
        float l = 0.0f;

        for (int j = 0; j < NK_; j++) {
            // QK dot: 16 x LDS.128, 32 x ffma2 in 4 chains
            const ulonglong2* kr2 = (const ulonglong2*)&Ks[j * DH_];
            unsigned long long s2a = 0ULL, s2b = 0ULL, s2c = 0ULL, s2d = 0ULL;
#pragma unroll
            for (int i = 0; i < 16; i += 2) {
                ulonglong2 t0v = kr2[i];
                ulonglong2 t1v = kr2[i + 1];
                s2a = ffma2(q2[2 * i + 0], t0v.x, s2a);
                s2b = ffma2(q2[2 * i + 1], t0v.y, s2b);
                s2c = ffma2(q2[2 * i + 2], t1v.x, s2c);
                s2d = ffma2(q2[2 * i + 3], t1v.y, s2d);
            }
            float a0, a1, b0, b1, c0, c1, d0, d1;
            unpackf2(s2a, a0, a1); unpackf2(s2b, b0, b1);
            unpackf2(s2c, c0, c1); unpackf2(s2d, d0, d1);
            float s = ((a0 + a1) + (b0 + b1)) + ((c0 + c1) + (d0 + d1));
            float p = __expf(s - m);
            l += p;
            unsigned long long p2 = packf2(p, p);
            // PV: 16 x LDS.128, 32 x ffma2
            const ulonglong2* vr2 = (const ulonglong2*)&Vs[j * DH_];
#pragma unroll
            for (int i = 0; i < 16; i++) {
                ulonglong2 t = vr2[i];
                acc2[2 * i + 0] = ffma2(p2, t.x, acc2[2 * i + 0]);
                acc2[2 * i + 1] = ffma2(p2, t.y, acc2[2 * i + 1]);
            }
        }

        const float inv = 1.0f / l;
        __nv_bfloat16* base = A2 + ((size_t)b * NTOT + qtok) * KP + hoff;
#pragma unroll
        for (int i = 0; i < 16; i++) {
            float v0, v1, v2, v3;
            unpackf2(acc2[2 * i], v0, v1);
            unpackf2(acc2[2 * i + 1], v2, v3);
            v0 *= inv; v1 *= inv; v2 *= inv; v3 *= inv;
            __nv_bfloat16 h0, h1, h2, h3, l0, l1, l2, l3;
            split_bf16(v0, h0, l0); split_bf16(v1, h1, l1);
            split_bf16(v2, h2, l2); split_bf16(v3, h3, l3);
            uint2 hp = make_uint2(pack2(h0, h1), pack2(h2, h3));
            uint2 lp = make_uint2(pack2(l0, l1), pack2(l2, l3));
            *(uint2*)(base + i * 4)        = hp;
            *(uint2*)(base + 512 + i * 4)  = lp;
            *(uint2*)(base + 1024 + i * 4) = hp;
        }
    } else {
        float* qs     = sh;
        float* sc     = sh + 64;
        float* redbuf = sh + 64 + NTOT;
        float* accs   = sh + 64 + NTOT + 8;

        const int cb = blockIdx.x - 512;
        const int b = cb / H_;
        const int h = cb % H_;
        const int lane = tid & 31;
        const int warp = tid >> 5;
        const size_t bbase = (size_t)b * NTOT * QKVC;
        const int hoff = h * DH_;

        if (tid < DH_) qs[tid] = qkv[bbase + hoff + tid] * 0.125f;
        __syncthreads();

        float lmax = -1e30f;
        for (int j = tid; j < NTOT; j += 256) {
            const float* kp = qkv + bbase + (size_t)j * QKVC + DIM_ + hoff;
            float s = 0.0f;
#pragma unroll
            for (int i = 0; i < 16; i++) {
                float4 kk = *(const float4*)&kp[i * 4];
                float4 qq = *(const float4*)&qs[i * 4];
                s += qq.x * kk.x + qq.y * kk.y + qq.z * kk.z + qq.w * kk.w;
            }
            sc[j] = s;
            lmax = fmaxf(lmax, s);
        }
#pragma unroll
        for (int o = 16; o; o >>= 1) lmax = fmaxf(lmax, __shfl_xor_sync(~0u, lmax, o));
        if (lane == 0) redbuf[warp] = lmax;
        __syncthreads();
        float m = fmaxf(fmaxf(fmaxf(redbuf[0], redbuf[1]), fmaxf(redbuf[2], redbuf[3])),
                        fmaxf(fmaxf(redbuf[4], redbuf[5]), fmaxf(redbuf[6], redbuf[7])));
        __syncthreads();

        float lsum = 0.0f;
        for (int j = tid; j < NTOT; j += 256) {
            float p = __expf(sc[j] - m);
            sc[j] = p;
            lsum += p;
        }
#pragma unroll
        for (int o = 16; o; o >>= 1) lsum += __shfl_xor_sync(~0u, lsum, o);
        if (lane == 0) redbuf[warp] = lsum;
        __syncthreads();
        float l = redbuf[0] + redbuf[1] + redbuf[2] + redbuf[3] +
                  redbuf[4] + redbuf[5] + redbuf[6] + redbuf[7];

        const int d = tid & 63;
        const int g = tid >> 6;
        float acc = 0.0f;
        for (int j = g; j < NTOT; j += 4)
            acc += sc[j] * qkv[bbase + (size_t)j * QKVC + 2 * DIM_ + hoff + d];
        accs[g * 64 + d] = acc;
        __syncthreads();
        if (tid < DH_) {
            float o = (accs[0 * 64 + tid] + accs[1 * 64 + tid] +
                       accs[2 * 64 + tid] + accs[3 * 64 + tid]) / l;
            __nv_bfloat16 hh, ll;
            split_bf16(o, hh, ll);
            __nv_bfloat16* base = A2 + (size_t)b * NTOT * KP + hoff + tid;
            base[0]    = hh;
            base[512]  = ll;
            base[1024] = hh;
        }
    }
}

// ---------------------------------------------------------------------------
extern "C" void kernel_launch(void* const* d_in, const int* in_sizes, int n_in,
                              void* d_out, int out_size) {
    const float* x    = (const float*)d_in[0];
    const float* Wqkv = (const float*)d_in[1];
    const float* Wout = (const float*)d_in[2];
    const float* bout = (const float*)d_in[3];
    float* out = (float*)d_out;

    float* qkv = nullptr;
    __nv_bfloat16 *A2x = nullptr, *A2att = nullptr, *B2qkv = nullptr, *B2out = nullptr;
    cudaGetSymbolAddress((void**)&qkv, g_qkv);
    cudaGetSymbolAddress((void**)&A2x, g_A2x);
    cudaGetSymbolAddress((void**)&A2att, g_A2att);
    cudaGetSymbolAddress((void**)&B2qkv, g_B2qkv);
    cudaGetSymbolAddress((void**)&B2out, g_B2out);

    // gemm<4,4,1>: stage = 48KB, 4 stages = 192KB, 1 CTA/SM
    constexpr int SM_BIG = 4 * (256 * 128 + 128 * 128);
    // gemm<1,4,2>: stage = 64*128 + 128*128 = 24KB, 4 stages = 96KB, 2 CTA/SM
    constexpr int SM_SML = 4 * (64 * 128 + 128 * 128);

    cudaFuncSetAttribute((const void*)&gemm_mma<4, 4, 1>,
                         cudaFuncAttributeMaxDynamicSharedMemorySize, SM_BIG);
    cudaFuncSetAttribute((const void*)&gemm_mma<1, 4, 2>,
                         cudaFuncAttributeMaxDynamicSharedMemorySize, SM_SML);

    // conversions
    {
        size_t tot = (size_t)MROWS * 128;
        conv_x_kernel<<<(unsigned)((tot + 255) / 256), 256>>>(x, A2x);
        convW_kernel<<<dim3(QKVC / 32, DIM_ / 32), dim3(32, 32)>>>(Wqkv, B2qkv, QKVC);
        convW_kernel<<<dim3(DIM_ / 32, DIM_ / 32), dim3(32, 32)>>>(Wout, B2out, DIM_);
    }

    // 1) qkv = x @ W_qkv  (256x128 tiles, 600 CTAs)
    gemm_mma<4, 4, 1><<<dim3(QKVC / 128, 50), 256, SM_BIG>>>(
        A2x, B2qkv, nullptr, qkv, MROWS, QKVC);

    // 2) attention: 512 local blocks + 32 cls blocks
    {
        int smem = 2 * NK_ * DH_ * (int)sizeof(float);   // 100864
        cudaFuncSetAttribute(attn_kernel,
                             cudaFuncAttributeMaxDynamicSharedMemorySize, smem);
        attn_kernel<<<B_ * H_ * F_ + B_ * H_, 256, smem>>>(qkv, A2att);
    }

    // 3) out = att @ W_out + b_out  (64x128 tiles, 792 CTAs, 2 CTA/SM)
    gemm_mma<1, 4, 2><<<dim3(DIM_ / 128, 198), 256, SM_SML>>>(
        A2att, B2out, bout, out, MROWS, DIM_);
}